// round 1
// baseline (speedup 1.0000x reference)
#include <cuda_runtime.h>
#include <math.h>

#define NN 512
#define LL 256
#define PP 64
#define CC 128   /* 2P */
#define HH 192   /* 3P */
#define OO 64
#define LNEPS 1e-5f

/* ---------------- scratch (no allocation allowed) ---------------- */
__device__ float g_lg[NN * CC];
__device__ float g_lv[NN * CC];
__device__ float g_rg[NN * CC];
__device__ float g_rv[NN * CC];
__device__ float g_left[NN * CC];
__device__ float g_right[NN * CC];
__device__ int   g_act[NN];
__device__ int   g_nact;

__device__ __forceinline__ float gelu_tanh(float x) {
    // jax.nn.gelu default (approximate=True): 0.5*x*(1+tanh(sqrt(2/pi)*(x+0.044715*x^3)))
    float u = 0.7978845608028654f * (x + 0.044715f * x * x * x);
    return 0.5f * x * (1.0f + tanhf(u));
}

/* ---------------- kernel 0: zero left/right accumulators ---------------- */
__global__ void k_zero() {
    int idx = blockIdx.x * blockDim.x + threadIdx.x;   // 256*256 = 65536 = NN*CC
    g_left[idx]  = 0.0f;
    g_right[idx] = 0.0f;
}

/* ---------------- kernel 1: deterministic mask compaction ---------------- */
__global__ void k_compact(const int* __restrict__ mask) {
    __shared__ int s[NN];
    int t = threadIdx.x;
    int m = mask[t] ? 1 : 0;
    s[t] = m;
    __syncthreads();
#pragma unroll
    for (int off = 1; off < NN; off <<= 1) {
        int v = (t >= off) ? s[t - off] : 0;
        __syncthreads();
        s[t] += v;
        __syncthreads();
    }
    if (m) g_act[s[t] - 1] = t;
    if (t == NN - 1) g_nact = s[NN - 1];
}

/* ---------------- kernel 2: LN(local) + 4 projections (lg/lv/rg/rv) ------ */
__global__ void __launch_bounds__(128) k_local(
    const float* __restrict__ local,
    const float* __restrict__ Wlg, const float* __restrict__ Wlv,
    const float* __restrict__ Wrg, const float* __restrict__ Wrv)
{
    __shared__ float ln_s[8 * LL];   // 8 rows
    __shared__ float red_s[8];
    int t = threadIdx.x;             // 128 threads
    int row0 = blockIdx.x * 8;
    int w = t >> 5;

    for (int r = 0; r < 8; ++r) {
        float x0 = local[(row0 + r) * LL + t];
        float x1 = local[(row0 + r) * LL + t + 128];
        float s = x0 + x1, q = x0 * x0 + x1 * x1;
#pragma unroll
        for (int off = 16; off; off >>= 1) {
            s += __shfl_xor_sync(0xffffffffu, s, off);
            q += __shfl_xor_sync(0xffffffffu, q, off);
        }
        if ((t & 31) == 0) { red_s[w] = s; red_s[4 + w] = q; }
        __syncthreads();
        float st = red_s[0] + red_s[1] + red_s[2] + red_s[3];
        float qt = red_s[4] + red_s[5] + red_s[6] + red_s[7];
        float mu = st * (1.0f / LL);
        float var = qt * (1.0f / LL) - mu * mu;
        float rstd = rsqrtf(var + LNEPS);
        ln_s[r * LL + t]       = (x0 - mu) * rstd;
        ln_s[r * LL + t + 128] = (x1 - mu) * rstd;
        __syncthreads();
    }

    const float* Ws[4] = { Wlg, Wlv, Wrg, Wrv };
    float* Os[4] = { g_lg, g_lv, g_rg, g_rv };
    int c = t;   // 0..127
#pragma unroll
    for (int m = 0; m < 4; ++m) {
        float acc[8] = {0, 0, 0, 0, 0, 0, 0, 0};
        const float* W = Ws[m];
        for (int k = 0; k < LL; ++k) {
            float wv = W[k * CC + c];
#pragma unroll
            for (int r = 0; r < 8; ++r) acc[r] += ln_s[r * LL + k] * wv;
        }
        float* Op = Os[m];
#pragma unroll
        for (int r = 0; r < 8; ++r) Op[(row0 + r) * CC + c] = acc[r];
    }
}

/* ---------------- kernel 3: fused pass-1 reduction over active pairs ----
   For each active (i,j): p = LN(pair[i,j]); pg = p@Wpg; pv = p@Wpv (in smem,
   never materialized to HBM); accumulate left[i] and right[j]. ----------- */
#define TI 16
#define TJ 16
__global__ void __launch_bounds__(256) k_pass1(
    const float* __restrict__ pair,
    const float* __restrict__ Wpg, const float* __restrict__ Wpv)
{
    extern __shared__ float sm[];
    float* Wg_s = sm;                      // 64*128
    float* Wv_s = Wg_s + PP * CC;          // 64*128
    float* lg_s = Wv_s + PP * CC;          // 16*128
    float* lv_s = lg_s + TI * CC;
    float* rg_s = lv_s + TJ * CC;
    float* rv_s = rg_s + TJ * CC;
    float* p_s  = rv_s + TI * CC;          // 8*64
    float* pg_s = p_s + 8 * PP;            // 8*128
    float* pv_s = pg_s + 8 * CC;           // 8*128
    float* lacc = pv_s + 8 * CC;           // 2*16*128

    int nact = g_nact;
    int bi0 = blockIdx.x * TI, bj0 = blockIdx.y * TJ;
    if (bi0 >= nact || bj0 >= nact) return;
    int ni = min(TI, nact - bi0), nj = min(TJ, nact - bj0);
    int t = threadIdx.x;

    for (int idx = t; idx < PP * CC; idx += 256) { Wg_s[idx] = Wpg[idx]; Wv_s[idx] = Wpv[idx]; }
    for (int idx = t; idx < TI * CC; idx += 256) {
        int r = idx >> 7, cc = idx & 127;
        float a = 0.f, b = 0.f, cv = 0.f, d = 0.f;
        if (r < ni) { int gi = g_act[bi0 + r]; a = g_lg[gi * CC + cc]; b = g_rv[gi * CC + cc]; }
        if (r < nj) { int gj = g_act[bj0 + r]; cv = g_lv[gj * CC + cc]; d = g_rg[gj * CC + cc]; }
        lg_s[idx] = a; rv_s[idx] = b; lv_s[idx] = cv; rg_s[idx] = d;
    }
    for (int idx = t; idx < 2 * TI * CC; idx += 256) lacc[idx] = 0.f;
    __syncthreads();

    int c = t & 127, h = t >> 7;
    int wid = t >> 5, lane = t & 31;
    int e0 = h * 4;
    float racc[8] = {0, 0, 0, 0, 0, 0, 0, 0};

    for (int il = 0; il < ni; ++il) {
        int gi = g_act[bi0 + il];
        const float* prow = pair + (size_t)gi * NN * PP;
        float lgv = lg_s[il * CC + c];
        float rvv = rv_s[il * CC + c];
        for (int jc = 0; jc < 2; ++jc) {
            /* LN stage: warp `wid` handles element wid (j_loc = jc*8+wid) */
            int jl = jc * 8 + wid;
            float x0 = 0.f, x1 = 0.f;
            if (jl < nj) {
                const float* pe = prow + (size_t)g_act[bj0 + jl] * PP;
                x0 = pe[lane]; x1 = pe[lane + 32];
            }
            float s = x0 + x1, q = x0 * x0 + x1 * x1;
#pragma unroll
            for (int off = 16; off; off >>= 1) {
                s += __shfl_xor_sync(0xffffffffu, s, off);
                q += __shfl_xor_sync(0xffffffffu, q, off);
            }
            float mu = s * (1.0f / PP);
            float rstd = rsqrtf(q * (1.0f / PP) - mu * mu + LNEPS);
            p_s[wid * PP + lane]      = (x0 - mu) * rstd;
            p_s[wid * PP + lane + 32] = (x1 - mu) * rstd;
            __syncthreads();

            /* GEMV stage: thread (c,h) computes pg/pv col c for elems e0..e0+3 */
            float ag0 = 0, ag1 = 0, ag2 = 0, ag3 = 0;
            float av0 = 0, av1 = 0, av2 = 0, av3 = 0;
#pragma unroll 4
            for (int k = 0; k < PP; ++k) {
                float wg = Wg_s[k * CC + c], wv = Wv_s[k * CC + c];
                float p0 = p_s[(e0 + 0) * PP + k];
                float p1 = p_s[(e0 + 1) * PP + k];
                float p2 = p_s[(e0 + 2) * PP + k];
                float p3 = p_s[(e0 + 3) * PP + k];
                ag0 += p0 * wg; av0 += p0 * wv;
                ag1 += p1 * wg; av1 += p1 * wv;
                ag2 += p2 * wg; av2 += p2 * wv;
                ag3 += p3 * wg; av3 += p3 * wv;
            }
            pg_s[(e0 + 0) * CC + c] = ag0; pv_s[(e0 + 0) * CC + c] = av0;
            pg_s[(e0 + 1) * CC + c] = ag1; pv_s[(e0 + 1) * CC + c] = av1;
            pg_s[(e0 + 2) * CC + c] = ag2; pv_s[(e0 + 2) * CC + c] = av2;
            pg_s[(e0 + 3) * CC + c] = ag3; pv_s[(e0 + 3) * CC + c] = av3;
            __syncthreads();

            /* elementwise gate*value + accumulate */
            float lsum = 0.f;
#pragma unroll
            for (int e = 0; e < 4; ++e) {
                int jl2 = jc * 8 + e0 + e;
                if (jl2 < nj) {
                    float pg = pg_s[(e0 + e) * CC + c];
                    float pv = pv_s[(e0 + e) * CC + c];
                    float gL = gelu_tanh(lgv + pg);
                    float vL = lv_s[jl2 * CC + c] + pv;
                    lsum += gL * vL;
                    float gR = gelu_tanh(rg_s[jl2 * CC + c] + pg);
                    racc[jc * 4 + e] += gR * (rvv + pv);
                }
            }
            lacc[h * (TI * CC) + il * CC + c] += lsum;
            __syncthreads();    /* protect p_s/pg_s reuse next chunk */
        }
    }

    /* flush right accumulators (8 per thread) */
#pragma unroll
    for (int jc = 0; jc < 2; ++jc)
#pragma unroll
        for (int e = 0; e < 4; ++e) {
            int jl = jc * 8 + e0 + e;
            if (jl < nj)
                atomicAdd(&g_right[(size_t)g_act[bj0 + jl] * CC + c], racc[jc * 4 + e]);
        }
    /* flush left accumulators (combine halves) */
    for (int idx = t; idx < ni * CC; idx += 256) {
        int il = idx >> 7, cc = idx & 127;
        atomicAdd(&g_left[(size_t)g_act[bi0 + il] * CC + cc],
                  lacc[idx] + lacc[TI * CC + idx]);
    }
}

/* ---------------- kernel 4: pass-2 — LN(pair), LN(left+right), out GEMM -- */
__global__ void __launch_bounds__(256) k_pass2(
    const float* __restrict__ pair,
    const float* __restrict__ Wout,
    float* __restrict__ out)
{
    extern __shared__ float sm[];
    float* W_s    = sm;                 // 192*64
    float* h_s    = W_s + HH * OO;      // 64*192  (hidden rows for 64 j's)
    float* left_s = h_s + 64 * HH;      // 128

    int t = threadIdx.x;
    int i  = blockIdx.y;                // 0..511
    int j0 = blockIdx.x * 64;           // 8 blocks of 64 j's

    for (int idx = t; idx < HH * OO; idx += 256) W_s[idx] = Wout[idx];
    if (t < CC) left_s[t] = g_left[i * CC + t];
    __syncthreads();

    int wid = t >> 5, lane = t & 31;
    /* stage A: 8 rounds x 8 warps -> hidden for 64 elements */
    for (int r = 0; r < 8; ++r) {
        int e = r * 8 + wid;
        int j = j0 + e;
        const float* pe = pair + ((size_t)i * NN + j) * PP;
        float x0 = pe[lane], x1 = pe[lane + 32];
        float s = x0 + x1, q = x0 * x0 + x1 * x1;
#pragma unroll
        for (int off = 16; off; off >>= 1) {
            s += __shfl_xor_sync(0xffffffffu, s, off);
            q += __shfl_xor_sync(0xffffffffu, q, off);
        }
        float mu = s * (1.0f / PP);
        float rstd = rsqrtf(q * (1.0f / PP) - mu * mu + LNEPS);
        h_s[e * HH + lane]      = (x0 - mu) * rstd;
        h_s[e * HH + lane + 32] = (x1 - mu) * rstd;

        const float* rr = &g_right[(size_t)j * CC];
        float y0 = left_s[lane]      + rr[lane];
        float y1 = left_s[lane + 32] + rr[lane + 32];
        float y2 = left_s[lane + 64] + rr[lane + 64];
        float y3 = left_s[lane + 96] + rr[lane + 96];
        s = y0 + y1 + y2 + y3;
        q = y0 * y0 + y1 * y1 + y2 * y2 + y3 * y3;
#pragma unroll
        for (int off = 16; off; off >>= 1) {
            s += __shfl_xor_sync(0xffffffffu, s, off);
            q += __shfl_xor_sync(0xffffffffu, q, off);
        }
        mu = s * (1.0f / CC);
        rstd = rsqrtf(q * (1.0f / CC) - mu * mu + LNEPS);
        h_s[e * HH + 64 + lane]      = (y0 - mu) * rstd;
        h_s[e * HH + 64 + lane + 32] = (y1 - mu) * rstd;
        h_s[e * HH + 64 + lane + 64] = (y2 - mu) * rstd;
        h_s[e * HH + 64 + lane + 96] = (y3 - mu) * rstd;
    }
    __syncthreads();

    /* stage B: register-tiled 4x4 GEMM (64 elems x 64 cols, K=192) */
    int cg = t & 15;    // cols cg*4 .. cg*4+3
    int eg = t >> 4;    // elems eg*4 .. eg*4+3
    float a00 = 0, a01 = 0, a02 = 0, a03 = 0;
    float a10 = 0, a11 = 0, a12 = 0, a13 = 0;
    float a20 = 0, a21 = 0, a22 = 0, a23 = 0;
    float a30 = 0, a31 = 0, a32 = 0, a33 = 0;
#pragma unroll 4
    for (int k = 0; k < HH; ++k) {
        float4 w = *(const float4*)&W_s[k * OO + cg * 4];
        float h0 = h_s[(eg * 4 + 0) * HH + k];
        float h1 = h_s[(eg * 4 + 1) * HH + k];
        float h2 = h_s[(eg * 4 + 2) * HH + k];
        float h3 = h_s[(eg * 4 + 3) * HH + k];
        a00 += h0 * w.x; a01 += h0 * w.y; a02 += h0 * w.z; a03 += h0 * w.w;
        a10 += h1 * w.x; a11 += h1 * w.y; a12 += h1 * w.z; a13 += h1 * w.w;
        a20 += h2 * w.x; a21 += h2 * w.y; a22 += h2 * w.z; a23 += h2 * w.w;
        a30 += h3 * w.x; a31 += h3 * w.y; a32 += h3 * w.z; a33 += h3 * w.w;
    }
    size_t base = ((size_t)i * NN + (j0 + eg * 4)) * OO + cg * 4;
    *(float4*)&out[base + 0 * OO] = make_float4(a00, a01, a02, a03);
    *(float4*)&out[base + 1 * OO] = make_float4(a10, a11, a12, a13);
    *(float4*)&out[base + 2 * OO] = make_float4(a20, a21, a22, a23);
    *(float4*)&out[base + 3 * OO] = make_float4(a30, a31, a32, a33);
}

/* ---------------- launch ---------------- */
extern "C" void kernel_launch(void* const* d_in, const int* in_sizes, int n_in,
                              void* d_out, int out_size)
{
    const float* local = (const float*)d_in[0];
    const float* pair  = (const float*)d_in[1];
    const int*   mask  = (const int*)d_in[2];
    const float* Wpg   = (const float*)d_in[3];
    const float* Wpv   = (const float*)d_in[4];
    const float* Wlg   = (const float*)d_in[5];
    const float* Wlv   = (const float*)d_in[6];
    const float* Wrg   = (const float*)d_in[7];
    const float* Wrv   = (const float*)d_in[8];
    const float* Wout  = (const float*)d_in[9];
    float* out = (float*)d_out;

    const int smem1 = (2 * PP * CC + 4 * TI * CC + 8 * PP + 2 * 8 * CC + 2 * TI * CC) * 4;
    const int smem2 = (HH * OO + 64 * HH + CC) * 4;
    static bool attr_done = false;
    if (!attr_done) {
        cudaFuncSetAttribute(k_pass1, cudaFuncAttributeMaxDynamicSharedMemorySize, smem1);
        cudaFuncSetAttribute(k_pass2, cudaFuncAttributeMaxDynamicSharedMemorySize, smem2);
        attr_done = true;
    }

    k_zero<<<256, 256>>>();
    k_compact<<<1, NN>>>(mask);
    k_local<<<64, 128>>>(local, Wlg, Wlv, Wrg, Wrv);
    k_pass1<<<dim3(NN / TI, NN / TJ), 256, smem1>>>(pair, Wpg, Wpv);
    k_pass2<<<dim3(NN / 64, NN), 256, smem2>>>(pair, Wout, out);
}

// round 4
// speedup vs baseline: 1.1685x; 1.1685x over previous
#include <cuda_runtime.h>
#include <cuda_bf16.h>
#include <math.h>
#include <stdint.h>

#define NN 512
#define LL 256
#define PP 64
#define CC 128   /* 2P */
#define HH 192   /* 3P */
#define OO 64
#define LNEPS 1e-5f

/* ---------------- scratch (no allocation allowed) ---------------- */
__device__ float g_lg[NN * CC];
__device__ float g_lv[NN * CC];
__device__ float g_rg[NN * CC];
__device__ float g_rv[NN * CC];
__device__ float g_left[NN * CC];
__device__ float g_right[NN * CC];
__device__ int   g_act[NN];
__device__ int   g_nact;

__device__ __forceinline__ float gelu_tanh(float x) {
    float u = 0.7978845608028654f * (x + 0.044715f * x * x * x);
    return 0.5f * x * (1.0f + tanhf(u));
}

/* ---------------- kernel 0: zero left/right accumulators ---------------- */
__global__ void k_zero() {
    int idx = blockIdx.x * blockDim.x + threadIdx.x;
    g_left[idx] = 0.0f;
    g_right[idx] = 0.0f;
}

/* ---------------- kernel 1: deterministic mask compaction ---------------- */
__global__ void k_compact(const int* __restrict__ mask) {
    __shared__ int s[NN];
    int t = threadIdx.x;
    int m = mask[t] ? 1 : 0;
    s[t] = m;
    __syncthreads();
#pragma unroll
    for (int off = 1; off < NN; off <<= 1) {
        int v = (t >= off) ? s[t - off] : 0;
        __syncthreads();
        s[t] += v;
        __syncthreads();
    }
    if (m) g_act[s[t] - 1] = t;
    if (t == NN - 1) g_nact = s[NN - 1];
}

/* ---------------- kernel 2: LN(local) + 4 projections ---------------- */
__global__ void __launch_bounds__(128) k_local(
    const float* __restrict__ local,
    const float* __restrict__ Wlg, const float* __restrict__ Wlv,
    const float* __restrict__ Wrg, const float* __restrict__ Wrv)
{
    __shared__ float ln_s[8 * LL];
    __shared__ float red_s[8];
    int t = threadIdx.x;
    int row0 = blockIdx.x * 8;
    int w = t >> 5;

    for (int r = 0; r < 8; ++r) {
        float x0 = local[(row0 + r) * LL + t];
        float x1 = local[(row0 + r) * LL + t + 128];
        float s = x0 + x1, q = x0 * x0 + x1 * x1;
#pragma unroll
        for (int off = 16; off; off >>= 1) {
            s += __shfl_xor_sync(0xffffffffu, s, off);
            q += __shfl_xor_sync(0xffffffffu, q, off);
        }
        if ((t & 31) == 0) { red_s[w] = s; red_s[4 + w] = q; }
        __syncthreads();
        float st = red_s[0] + red_s[1] + red_s[2] + red_s[3];
        float qt = red_s[4] + red_s[5] + red_s[6] + red_s[7];
        float mu = st * (1.0f / LL);
        float var = qt * (1.0f / LL) - mu * mu;
        float rstd = rsqrtf(var + LNEPS);
        ln_s[r * LL + t]       = (x0 - mu) * rstd;
        ln_s[r * LL + t + 128] = (x1 - mu) * rstd;
        __syncthreads();
    }

    const float* Ws[4] = { Wlg, Wlv, Wrg, Wrv };
    float* Os[4] = { g_lg, g_lv, g_rg, g_rv };
    int c = t;
#pragma unroll
    for (int m = 0; m < 4; ++m) {
        float acc[8] = {0, 0, 0, 0, 0, 0, 0, 0};
        const float* W = Ws[m];
        for (int k = 0; k < LL; ++k) {
            float wv = W[k * CC + c];
#pragma unroll
            for (int r = 0; r < 8; ++r) acc[r] += ln_s[r * LL + k] * wv;
        }
        float* Op = Os[m];
#pragma unroll
        for (int r = 0; r < 8; ++r) Op[(row0 + r) * CC + c] = acc[r];
    }
}

/* ---------------- kernel 3: fused pass-1 (scalar FFMA, register epilogue)
   smem: Wg(32K) Wv(32K) lg/lv/rg/rv(8K each) p(2K) lacc(8K) = 106KB -> 2 CTA/SM */
#define TI 16
__global__ void __launch_bounds__(256, 2) k_pass1(
    const float* __restrict__ pair,
    const float* __restrict__ Wpg, const float* __restrict__ Wpv)
{
    extern __shared__ float sm[];
    float* Wg_s = sm;                       // 8192 floats
    float* Wv_s = Wg_s + PP * CC;           // 8192
    float* lg_s = Wv_s + PP * CC;           // 2048
    float* lv_s = lg_s + TI * CC;
    float* rg_s = lv_s + TI * CC;
    float* rv_s = rg_s + TI * CC;
    float* p_s  = rv_s + TI * CC;           // 512  (8 elems x 64)
    float* lacc = p_s + 8 * PP;             // 2048

    int nact = g_nact;
    int bi0 = blockIdx.x * TI, bj0 = blockIdx.y * TI;
    if (bi0 >= nact || bj0 >= nact) return;
    int ni = min(TI, nact - bi0), nj = min(TI, nact - bj0);
    int t = threadIdx.x;

    for (int idx = t; idx < PP * CC; idx += 256) { Wg_s[idx] = Wpg[idx]; Wv_s[idx] = Wpv[idx]; }
    for (int idx = t; idx < TI * CC; idx += 256) {
        int r = idx >> 7, cc = idx & 127;
        float a = 0.f, b = 0.f, cv = 0.f, d = 0.f;
        if (r < ni) { int gi = g_act[bi0 + r]; a = g_lg[gi * CC + cc]; b = g_rv[gi * CC + cc]; }
        if (r < nj) { int gj = g_act[bj0 + r]; cv = g_lv[gj * CC + cc]; d = g_rg[gj * CC + cc]; }
        lg_s[idx] = a; rv_s[idx] = b; lv_s[idx] = cv; rg_s[idx] = d;
    }
    for (int idx = t; idx < TI * CC; idx += 256) lacc[idx] = 0.f;
    __syncthreads();

    int c2 = t & 63;            // column pair: cols 2*c2, 2*c2+1
    int g  = t >> 6;            // elem group: elems 2g, 2g+1 of each 8-chunk
    int wid = t >> 5, lane = t & 31;
    float racc[8] = {0, 0, 0, 0, 0, 0, 0, 0};

    const float2* wg2 = (const float2*)Wg_s;
    const float2* wv2 = (const float2*)Wv_s;

    for (int il = 0; il < ni; ++il) {
        int gi = g_act[bi0 + il];
        const float* prow = pair + (size_t)gi * NN * PP;
        float lgv0 = lg_s[il * CC + 2 * c2], lgv1 = lg_s[il * CC + 2 * c2 + 1];
        float rvv0 = rv_s[il * CC + 2 * c2], rvv1 = rv_s[il * CC + 2 * c2 + 1];
        float lsum0 = 0.f, lsum1 = 0.f;
#pragma unroll
        for (int jc = 0; jc < 2; ++jc) {
            /* LN: warp wid handles elem jl = jc*8+wid */
            int jl = jc * 8 + wid;
            float2 x = make_float2(0.f, 0.f);
            if (jl < nj) x = *(const float2*)(prow + (size_t)g_act[bj0 + jl] * PP + 2 * lane);
            float s = x.x + x.y, q = x.x * x.x + x.y * x.y;
#pragma unroll
            for (int off = 16; off; off >>= 1) {
                s += __shfl_xor_sync(0xffffffffu, s, off);
                q += __shfl_xor_sync(0xffffffffu, q, off);
            }
            float mu = s * (1.0f / PP);
            float rstd = rsqrtf(q * (1.0f / PP) - mu * mu + LNEPS);
            *(float2*)(p_s + wid * PP + 2 * lane) =
                make_float2((x.x - mu) * rstd, (x.y - mu) * rstd);
            __syncthreads();

            /* GEMV: elems 2g,2g+1, cols 2c2,2c2+1, both mats (8 accums) */
            float ag0x = 0, ag0y = 0, av0x = 0, av0y = 0;
            float ag1x = 0, ag1y = 0, av1x = 0, av1y = 0;
            const float* pr0 = p_s + (2 * g) * PP;
            const float* pr1 = pr0 + PP;
#pragma unroll 8
            for (int k = 0; k < PP; ++k) {
                float2 wg = wg2[k * (CC / 2) + c2];
                float2 wv = wv2[k * (CC / 2) + c2];
                float p0 = pr0[k], p1 = pr1[k];
                ag0x += p0 * wg.x; ag0y += p0 * wg.y;
                av0x += p0 * wv.x; av0y += p0 * wv.y;
                ag1x += p1 * wg.x; ag1y += p1 * wg.y;
                av1x += p1 * wv.x; av1y += p1 * wv.y;
            }

            /* elementwise (in registers) */
#pragma unroll
            for (int el = 0; el < 2; ++el) {
                int jl2 = jc * 8 + 2 * g + el;
                if (jl2 < nj) {
                    float pgA = el ? ag1x : ag0x, pgB = el ? ag1y : ag0y;
                    float pvA = el ? av1x : av0x, pvB = el ? av1y : av0y;
                    float2 lv2 = *(const float2*)(lv_s + jl2 * CC + 2 * c2);
                    float2 rg2 = *(const float2*)(rg_s + jl2 * CC + 2 * c2);
                    lsum0 += gelu_tanh(lgv0 + pgA) * (lv2.x + pvA);
                    lsum1 += gelu_tanh(lgv1 + pgB) * (lv2.y + pvB);
                    racc[jc * 4 + el * 2 + 0] += gelu_tanh(rg2.x + pgA) * (rvv0 + pvA);
                    racc[jc * 4 + el * 2 + 1] += gelu_tanh(rg2.y + pgB) * (rvv1 + pvB);
                }
            }
            __syncthreads();   /* protect p_s before next chunk overwrites */
        }
        atomicAdd(&lacc[il * CC + 2 * c2], lsum0);
        atomicAdd(&lacc[il * CC + 2 * c2 + 1], lsum1);
    }

    /* flush right */
#pragma unroll
    for (int jc = 0; jc < 2; ++jc)
#pragma unroll
        for (int el = 0; el < 2; ++el) {
            int jl = jc * 8 + 2 * g + el;
            if (jl < nj) {
                float* rp = &g_right[(size_t)g_act[bj0 + jl] * CC + 2 * c2];
                atomicAdd(rp, racc[jc * 4 + el * 2 + 0]);
                atomicAdd(rp + 1, racc[jc * 4 + el * 2 + 1]);
            }
        }
    __syncthreads();
    /* flush left */
    for (int idx = t; idx < ni * CC; idx += 256) {
        int il = idx >> 7, cc = idx & 127;
        atomicAdd(&g_left[(size_t)g_act[bi0 + il] * CC + cc], lacc[idx]);
    }
}

/* ---------------- kernel 4: pass-2 via mma.sync bf16 3-term -------------
   Per CTA: i = blockIdx.y, 128 j's. H [128 x 192] bf16 hi/lo in padded smem
   (row stride 100 words), Bt = Wout^T [64 x 192] hi/lo. 8 warps x 16 rows.
   D = Ah*Bh + Al*Bh + Ah*Bl accumulated in f32 fragments.               */
#define HSTRIDE 100                     /* words per row (192 halves = 96 + pad) */
#define HHI_OFF  0
#define HLO_OFF  12800
#define BTHI_OFF 25600
#define BTLO_OFF 32000
#define LEFT_OFF 38400
#define SMEM2_FLOATS 38528

__device__ __forceinline__ uint32_t pack_hi_split(float x0, float x1, uint32_t& lo_out) {
    __nv_bfloat16 h0 = __float2bfloat16_rn(x0);
    __nv_bfloat16 h1 = __float2bfloat16_rn(x1);
    __nv_bfloat16 l0 = __float2bfloat16_rn(x0 - __bfloat162float(h0));
    __nv_bfloat16 l1 = __float2bfloat16_rn(x1 - __bfloat162float(h1));
    lo_out = ((uint32_t)__bfloat16_as_ushort(l1) << 16) | __bfloat16_as_ushort(l0);
    return ((uint32_t)__bfloat16_as_ushort(h1) << 16) | __bfloat16_as_ushort(h0);
}

#define MMA_BF16(acc, a0, a1, a2, a3, b0, b1) \
    asm volatile("mma.sync.aligned.m16n8k16.row.col.f32.bf16.bf16.f32 " \
        "{%0,%1,%2,%3}, {%4,%5,%6,%7}, {%8,%9}, {%0,%1,%2,%3};" \
        : "+f"((acc)[0]), "+f"((acc)[1]), "+f"((acc)[2]), "+f"((acc)[3]) \
        : "r"(a0), "r"(a1), "r"(a2), "r"(a3), "r"(b0), "r"(b1))

__global__ void __launch_bounds__(256) k_pass2(
    const float* __restrict__ pair,
    const float* __restrict__ Wout,
    float* __restrict__ out)
{
    extern __shared__ float sm2[];
    uint32_t* Hhi  = (uint32_t*)(sm2 + HHI_OFF);
    uint32_t* Hlo  = (uint32_t*)(sm2 + HLO_OFF);
    uint32_t* Bthi = (uint32_t*)(sm2 + BTHI_OFF);
    uint32_t* Btlo = (uint32_t*)(sm2 + BTLO_OFF);
    float* left_s  = sm2 + LEFT_OFF;

    int t = threadIdx.x;
    int wid = t >> 5, lane = t & 31;
    int i = blockIdx.y;
    int j0 = blockIdx.x * 128;

    if (t < CC) left_s[t] = g_left[(size_t)i * CC + t];

    /* Bt[n][k] = Wout[k][n], bf16 hi/lo, padded stride */
    for (int idx = t; idx < 96 * 64; idx += 256) {
        int kp = idx >> 6, n = idx & 63;
        int k = kp * 2;
        uint32_t lo;
        uint32_t hi = pack_hi_split(Wout[k * OO + n], Wout[(k + 1) * OO + n], lo);
        Bthi[n * HSTRIDE + kp] = hi;
        Btlo[n * HSTRIDE + kp] = lo;
    }
    __syncthreads();   /* covers left_s too */

    /* H stage: 16 rounds x 8 warps -> 128 rows, 1-ahead prefetch */
    const float* pbase = pair + ((size_t)i * NN + j0) * PP;
    const float* rbase = g_right + (size_t)j0 * CC;
    float2 px = *(const float2*)(pbase + (size_t)wid * PP + 2 * lane);
    float4 rx = *(const float4*)(rbase + (size_t)wid * CC + 4 * lane);
    for (int r = 0; r < 16; ++r) {
        int e = r * 8 + wid;
        float2 cp = px; float4 cr = rx;
        if (r < 15) {
            px = *(const float2*)(pbase + (size_t)(e + 8) * PP + 2 * lane);
            rx = *(const float4*)(rbase + (size_t)(e + 8) * CC + 4 * lane);
        }
        /* LN(pair row) over 64 */
        float s = cp.x + cp.y, q = cp.x * cp.x + cp.y * cp.y;
#pragma unroll
        for (int off = 16; off; off >>= 1) {
            s += __shfl_xor_sync(0xffffffffu, s, off);
            q += __shfl_xor_sync(0xffffffffu, q, off);
        }
        float mu = s * (1.0f / PP);
        float rstd = rsqrtf(q * (1.0f / PP) - mu * mu + LNEPS);
        {
            uint32_t lo;
            uint32_t hi = pack_hi_split((cp.x - mu) * rstd, (cp.y - mu) * rstd, lo);
            Hhi[e * HSTRIDE + lane] = hi;
            Hlo[e * HSTRIDE + lane] = lo;
        }
        /* LN(left+right) over 128 */
        float y0 = left_s[4 * lane]     + cr.x;
        float y1 = left_s[4 * lane + 1] + cr.y;
        float y2 = left_s[4 * lane + 2] + cr.z;
        float y3 = left_s[4 * lane + 3] + cr.w;
        s = y0 + y1 + y2 + y3;
        q = y0 * y0 + y1 * y1 + y2 * y2 + y3 * y3;
#pragma unroll
        for (int off = 16; off; off >>= 1) {
            s += __shfl_xor_sync(0xffffffffu, s, off);
            q += __shfl_xor_sync(0xffffffffu, q, off);
        }
        mu = s * (1.0f / CC);
        rstd = rsqrtf(q * (1.0f / CC) - mu * mu + LNEPS);
        {
            uint32_t lo0, lo1;
            uint32_t hi0 = pack_hi_split((y0 - mu) * rstd, (y1 - mu) * rstd, lo0);
            uint32_t hi1 = pack_hi_split((y2 - mu) * rstd, (y3 - mu) * rstd, lo1);
            int wbase = e * HSTRIDE + 32 + 2 * lane;
            *(uint2*)(Hhi + wbase) = make_uint2(hi0, hi1);
            *(uint2*)(Hlo + wbase) = make_uint2(lo0, lo1);
        }
    }
    __syncthreads();

    /* MMA stage: warp wid -> rows wr..wr+15; 8 n-tiles; K=192 (12 steps) */
    int wr = wid * 16;
    int grp = lane >> 2, qid = lane & 3;
    float acc[8][4];
#pragma unroll
    for (int nt = 0; nt < 8; ++nt)
#pragma unroll
        for (int cqd = 0; cqd < 4; ++cqd) acc[nt][cqd] = 0.f;

#pragma unroll 2
    for (int ks = 0; ks < 12; ++ks) {
        int rb0 = (wr + grp) * HSTRIDE + ks * 8 + qid;
        int rb1 = rb0 + 8 * HSTRIDE;
        uint32_t ah0 = Hhi[rb0], ah1 = Hhi[rb1], ah2 = Hhi[rb0 + 4], ah3 = Hhi[rb1 + 4];
        uint32_t al0 = Hlo[rb0], al1 = Hlo[rb1], al2 = Hlo[rb0 + 4], al3 = Hlo[rb1 + 4];
#pragma unroll
        for (int nt = 0; nt < 8; ++nt) {
            int bo = (nt * 8 + grp) * HSTRIDE + ks * 8 + qid;
            uint32_t bh0 = Bthi[bo], bh1 = Bthi[bo + 4];
            uint32_t bl0 = Btlo[bo], bl1 = Btlo[bo + 4];
            MMA_BF16(acc[nt], ah0, ah1, ah2, ah3, bh0, bh1);
            MMA_BF16(acc[nt], al0, al1, al2, al3, bh0, bh1);
            MMA_BF16(acc[nt], ah0, ah1, ah2, ah3, bl0, bl1);
        }
    }

    /* store fragments directly */
    size_t orow0 = ((size_t)i * NN + j0 + wr + grp) * OO;
    size_t orow1 = orow0 + 8 * OO;
#pragma unroll
    for (int nt = 0; nt < 8; ++nt) {
        int col = nt * 8 + qid * 2;
        *(float2*)(out + orow0 + col) = make_float2(acc[nt][0], acc[nt][1]);
        *(float2*)(out + orow1 + col) = make_float2(acc[nt][2], acc[nt][3]);
    }
}

/* ---------------- launch ---------------- */
extern "C" void kernel_launch(void* const* d_in, const int* in_sizes, int n_in,
                              void* d_out, int out_size)
{
    const float* local = (const float*)d_in[0];
    const float* pair  = (const float*)d_in[1];
    const int*   mask  = (const int*)d_in[2];
    const float* Wpg   = (const float*)d_in[3];
    const float* Wpv   = (const float*)d_in[4];
    const float* Wlg   = (const float*)d_in[5];
    const float* Wlv   = (const float*)d_in[6];
    const float* Wrg   = (const float*)d_in[7];
    const float* Wrv   = (const float*)d_in[8];
    const float* Wout  = (const float*)d_in[9];
    float* out = (float*)d_out;

    const int smem1 = (2 * PP * CC + 4 * TI * CC + 8 * PP + TI * CC) * 4;  /* 108544 */
    const int smem2 = SMEM2_FLOATS * 4;                                    /* 154112 */
    static bool attr_done = false;
    if (!attr_done) {
        cudaFuncSetAttribute(k_pass1, cudaFuncAttributeMaxDynamicSharedMemorySize, smem1);
        cudaFuncSetAttribute(k_pass2, cudaFuncAttributeMaxDynamicSharedMemorySize, smem2);
        attr_done = true;
    }

    k_zero<<<256, 256>>>();
    k_compact<<<1, NN>>>(mask);
    k_local<<<64, 128>>>(local, Wlg, Wlv, Wrg, Wrv);
    k_pass1<<<dim3(NN / TI, NN / TI), 256, smem1>>>(pair, Wpg, Wpv);
    k_pass2<<<dim3(NN / 128, NN), 256, smem2>>>(pair, Wout, out);
}

// round 5
// speedup vs baseline: 1.3666x; 1.1696x over previous
#include <cuda_runtime.h>
#include <cuda_bf16.h>
#include <math.h>
#include <stdint.h>

#define NN 512
#define LL 256
#define PP 64
#define CC 128   /* 2P */
#define HH 192   /* 3P */
#define OO 64
#define LNEPS 1e-5f

/* ---------------- scratch (no allocation allowed) ---------------- */
__device__ float g_lg[NN * CC];
__device__ float g_lv[NN * CC];
__device__ float g_rg[NN * CC];
__device__ float g_rv[NN * CC];
__device__ float g_left[NN * CC];
__device__ float g_right[NN * CC];
__device__ int   g_act[NN];
__device__ int   g_nact;

#define HSTRIDE 100
__device__ __align__(16) uint32_t g_bthi[OO * HSTRIDE];
__device__ __align__(16) uint32_t g_btlo[OO * HSTRIDE];

__device__ __forceinline__ float gelu_fast(float x) {
    /* jax.nn.gelu approximate=True, tanh via MUFU.TANH (abs err ~2^-11) */
    float u = 0.7978845608028654f * (x + 0.044715f * x * x * x);
    float th;
    asm("tanh.approx.f32 %0, %1;" : "=f"(th) : "f"(u));
    return 0.5f * x * (1.0f + th);
}

__device__ __forceinline__ uint32_t pack_hi_split(float x0, float x1, uint32_t& lo_out) {
    __nv_bfloat16 h0 = __float2bfloat16_rn(x0);
    __nv_bfloat16 h1 = __float2bfloat16_rn(x1);
    __nv_bfloat16 l0 = __float2bfloat16_rn(x0 - __bfloat162float(h0));
    __nv_bfloat16 l1 = __float2bfloat16_rn(x1 - __bfloat162float(h1));
    lo_out = ((uint32_t)__bfloat16_as_ushort(l1) << 16) | __bfloat16_as_ushort(l0);
    return ((uint32_t)__bfloat16_as_ushort(h1) << 16) | __bfloat16_as_ushort(h0);
}

#define MMA_BF16(acc, a0, a1, a2, a3, b0, b1) \
    asm volatile("mma.sync.aligned.m16n8k16.row.col.f32.bf16.bf16.f32 " \
        "{%0,%1,%2,%3}, {%4,%5,%6,%7}, {%8,%9}, {%0,%1,%2,%3};" \
        : "+f"((acc)[0]), "+f"((acc)[1]), "+f"((acc)[2]), "+f"((acc)[3]) \
        : "r"(a0), "r"(a1), "r"(a2), "r"(a3), "r"(b0), "r"(b1))

/* ---------------- kernel 0: zero accumulators ---------------- */
__global__ void k_zero() {
    int idx = blockIdx.x * blockDim.x + threadIdx.x;
    g_left[idx] = 0.0f;
    g_right[idx] = 0.0f;
}

/* ---------------- kernel 1: mask compaction ---------------- */
__global__ void k_compact(const int* __restrict__ mask) {
    __shared__ int s[NN];
    int t = threadIdx.x;
    int m = mask[t] ? 1 : 0;
    s[t] = m;
    __syncthreads();
#pragma unroll
    for (int off = 1; off < NN; off <<= 1) {
        int v = (t >= off) ? s[t - off] : 0;
        __syncthreads();
        s[t] += v;
        __syncthreads();
    }
    if (m) g_act[s[t] - 1] = t;
    if (t == NN - 1) g_nact = s[NN - 1];
}

/* ---------------- kernel 1b: Wout -> bf16 hi/lo split (once) ---------- */
__global__ void k_prepb(const float* __restrict__ Wout) {
    int idx = blockIdx.x * 256 + threadIdx.x;
    if (idx >= 96 * 64) return;
    int kp = idx >> 6, n = idx & 63;
    int k = kp * 2;
    uint32_t lo;
    uint32_t hi = pack_hi_split(Wout[k * OO + n], Wout[(k + 1) * OO + n], lo);
    g_bthi[n * HSTRIDE + kp] = hi;
    g_btlo[n * HSTRIDE + kp] = lo;
}

/* ---------------- kernel 2: LN(local) + 4 projections ---------------- */
__global__ void __launch_bounds__(128) k_local(
    const float* __restrict__ local,
    const float* __restrict__ Wlg, const float* __restrict__ Wlv,
    const float* __restrict__ Wrg, const float* __restrict__ Wrv)
{
    __shared__ float ln_s[8 * LL];
    __shared__ float red_s[8];
    int t = threadIdx.x;
    int row0 = blockIdx.x * 8;
    int w = t >> 5;

    for (int r = 0; r < 8; ++r) {
        float x0 = local[(row0 + r) * LL + t];
        float x1 = local[(row0 + r) * LL + t + 128];
        float s = x0 + x1, q = x0 * x0 + x1 * x1;
#pragma unroll
        for (int off = 16; off; off >>= 1) {
            s += __shfl_xor_sync(0xffffffffu, s, off);
            q += __shfl_xor_sync(0xffffffffu, q, off);
        }
        if ((t & 31) == 0) { red_s[w] = s; red_s[4 + w] = q; }
        __syncthreads();
        float st = red_s[0] + red_s[1] + red_s[2] + red_s[3];
        float qt = red_s[4] + red_s[5] + red_s[6] + red_s[7];
        float mu = st * (1.0f / LL);
        float var = qt * (1.0f / LL) - mu * mu;
        float rstd = rsqrtf(var + LNEPS);
        ln_s[r * LL + t]       = (x0 - mu) * rstd;
        ln_s[r * LL + t + 128] = (x1 - mu) * rstd;
        __syncthreads();
    }

    const float* Ws[4] = { Wlg, Wlv, Wrg, Wrv };
    float* Os[4] = { g_lg, g_lv, g_rg, g_rv };
    int c = t;
#pragma unroll
    for (int m = 0; m < 4; ++m) {
        float acc[8] = {0, 0, 0, 0, 0, 0, 0, 0};
        const float* W = Ws[m];
        for (int k = 0; k < LL; ++k) {
            float wv = W[k * CC + c];
#pragma unroll
            for (int r = 0; r < 8; ++r) acc[r] += ln_s[r * LL + k] * wv;
        }
        float* Op = Os[m];
#pragma unroll
        for (int r = 0; r < 8; ++r) Op[(row0 + r) * CC + c] = acc[r];
    }
}

/* ---------------- kernel 3: fused pass-1 ------------------------------
   thread map: cg = t>>3 (4 cols), el = t&7 (1 elem of 8-chunk)
   p_s double-buffered (stride 68), 1 sync per chunk.
   smem: 2*8192 + 4*2048 + 1088 + 2048 = 27712 floats = 110848 B -> 2 CTA/SM */
#define TI 16
#define PSTR 68
__global__ void __launch_bounds__(256, 2) k_pass1(
    const float* __restrict__ pair,
    const float* __restrict__ Wpg, const float* __restrict__ Wpv)
{
    extern __shared__ float sm[];
    float* Wg_s = sm;                       // 8192
    float* Wv_s = Wg_s + PP * CC;           // 8192
    float* lg_s = Wv_s + PP * CC;           // 2048
    float* lv_s = lg_s + TI * CC;
    float* rg_s = lv_s + TI * CC;
    float* rv_s = rg_s + TI * CC;
    float* p_s  = rv_s + TI * CC;           // 2*8*68 = 1088
    float* lacc = p_s + 2 * 8 * PSTR;       // 2048

    int nact = g_nact;
    int bi0 = blockIdx.x * TI, bj0 = blockIdx.y * TI;
    if (bi0 >= nact || bj0 >= nact) return;
    int ni = min(TI, nact - bi0), nj = min(TI, nact - bj0);
    int t = threadIdx.x;

    for (int idx = t; idx < PP * CC; idx += 256) { Wg_s[idx] = Wpg[idx]; Wv_s[idx] = Wpv[idx]; }
    for (int idx = t; idx < TI * CC; idx += 256) {
        int r = idx >> 7, cc = idx & 127;
        float a = 0.f, b = 0.f, cv = 0.f, d = 0.f;
        if (r < ni) { int gi = g_act[bi0 + r]; a = g_lg[gi * CC + cc]; b = g_rv[gi * CC + cc]; }
        if (r < nj) { int gj = g_act[bj0 + r]; cv = g_lv[gj * CC + cc]; d = g_rg[gj * CC + cc]; }
        lg_s[idx] = a; rv_s[idx] = b; lv_s[idx] = cv; rg_s[idx] = d;
    }
    for (int idx = t; idx < TI * CC; idx += 256) lacc[idx] = 0.f;
    __syncthreads();

    int cg = t >> 3;            // 0..31: cols cg*4..cg*4+3
    int el = t & 7;             // elem within 8-chunk
    int wid = t >> 5, lane = t & 31;
    const float4* wgq = (const float4*)Wg_s;
    const float4* wvq = (const float4*)Wv_s;
    float4 racc0 = make_float4(0, 0, 0, 0);
    float4 racc1 = make_float4(0, 0, 0, 0);

    for (int il = 0; il < ni; ++il) {
        int gi = g_act[bi0 + il];
        const float* prow = pair + (size_t)gi * NN * PP;
        float4 lg4 = *(const float4*)(lg_s + il * CC + cg * 4);
        float4 rv4 = *(const float4*)(rv_s + il * CC + cg * 4);
        float4 lsum = make_float4(0, 0, 0, 0);
#pragma unroll
        for (int jc = 0; jc < 2; ++jc) {
            int buf = (il * 2 + jc) & 1;
            /* LN: warp wid handles elem jl = jc*8+wid */
            int jl = jc * 8 + wid;
            float2 x = make_float2(0.f, 0.f);
            if (jl < nj) x = *(const float2*)(prow + (size_t)g_act[bj0 + jl] * PP + 2 * lane);
            float s = x.x + x.y, q = x.x * x.x + x.y * x.y;
#pragma unroll
            for (int off = 16; off; off >>= 1) {
                s += __shfl_xor_sync(0xffffffffu, s, off);
                q += __shfl_xor_sync(0xffffffffu, q, off);
            }
            float mu = s * (1.0f / PP);
            float rstd = rsqrtf(q * (1.0f / PP) - mu * mu + LNEPS);
            *(float2*)(p_s + buf * (8 * PSTR) + wid * PSTR + 2 * lane) =
                make_float2((x.x - mu) * rstd, (x.y - mu) * rstd);
            __syncthreads();

            /* GEMV: this thread -> elem el, cols cg*4..+3, both mats */
            const float* pp = p_s + buf * (8 * PSTR) + el * PSTR;
            float4 pg = make_float4(0, 0, 0, 0);
            float4 pv = make_float4(0, 0, 0, 0);
#pragma unroll 8
            for (int k = 0; k < PP; ++k) {
                float4 wg = wgq[k * 32 + cg];
                float4 wv = wvq[k * 32 + cg];
                float p = pp[k];
                pg.x += p * wg.x; pg.y += p * wg.y; pg.z += p * wg.z; pg.w += p * wg.w;
                pv.x += p * wv.x; pv.y += p * wv.y; pv.z += p * wv.z; pv.w += p * wv.w;
            }

            int jl2 = jc * 8 + el;
            if (jl2 < nj) {
                float4 lv4 = *(const float4*)(lv_s + jl2 * CC + cg * 4);
                float4 rg4 = *(const float4*)(rg_s + jl2 * CC + cg * 4);
                lsum.x += gelu_fast(lg4.x + pg.x) * (lv4.x + pv.x);
                lsum.y += gelu_fast(lg4.y + pg.y) * (lv4.y + pv.y);
                lsum.z += gelu_fast(lg4.z + pg.z) * (lv4.z + pv.z);
                lsum.w += gelu_fast(lg4.w + pg.w) * (lv4.w + pv.w);
                float4& ra = jc ? racc1 : racc0;
                ra.x += gelu_fast(rg4.x + pg.x) * (rv4.x + pv.x);
                ra.y += gelu_fast(rg4.y + pg.y) * (rv4.y + pv.y);
                ra.z += gelu_fast(rg4.z + pg.z) * (rv4.z + pv.z);
                ra.w += gelu_fast(rg4.w + pg.w) * (rv4.w + pv.w);
            }
        }
        /* reduce lsum over el (lane bits 0..2), single writer adds to lacc */
#pragma unroll
        for (int off = 1; off < 8; off <<= 1) {
            lsum.x += __shfl_xor_sync(0xffffffffu, lsum.x, off);
            lsum.y += __shfl_xor_sync(0xffffffffu, lsum.y, off);
            lsum.z += __shfl_xor_sync(0xffffffffu, lsum.z, off);
            lsum.w += __shfl_xor_sync(0xffffffffu, lsum.w, off);
        }
        if (el == 0) {
            float* lp = lacc + il * CC + cg * 4;
            lp[0] += lsum.x; lp[1] += lsum.y; lp[2] += lsum.z; lp[3] += lsum.w;
        }
    }

    /* flush right */
#pragma unroll
    for (int jc = 0; jc < 2; ++jc) {
        int jl = jc * 8 + el;
        if (jl < nj) {
            float* rp = &g_right[(size_t)g_act[bj0 + jl] * CC + cg * 4];
            float4 ra = jc ? racc1 : racc0;
            atomicAdd(rp + 0, ra.x);
            atomicAdd(rp + 1, ra.y);
            atomicAdd(rp + 2, ra.z);
            atomicAdd(rp + 3, ra.w);
        }
    }
    __syncthreads();
    /* flush left */
    for (int idx = t; idx < ni * CC; idx += 256) {
        int il = idx >> 7, cc = idx & 127;
        atomicAdd(&g_left[(size_t)g_act[bi0 + il] * CC + cc], lacc[idx]);
    }
}

/* ---------------- kernel 4: pass-2, 512 threads, split-chain HMMA ------ */
#define HHI_OFF  0
#define HLO_OFF  12800
#define BTHI_OFF 25600
#define BTLO_OFF 32000
#define LEFT_OFF 38400
#define SMEM2_FLOATS 38528

__global__ void __launch_bounds__(512) k_pass2(
    const float* __restrict__ pair,
    float* __restrict__ out)
{
    extern __shared__ float sm2[];
    uint32_t* Hhi  = (uint32_t*)(sm2 + HHI_OFF);
    uint32_t* Hlo  = (uint32_t*)(sm2 + HLO_OFF);
    uint32_t* Bthi = (uint32_t*)(sm2 + BTHI_OFF);
    uint32_t* Btlo = (uint32_t*)(sm2 + BTLO_OFF);
    float* left_s  = sm2 + LEFT_OFF;

    int t = threadIdx.x;
    int wid = t >> 5, lane = t & 31;
    int i = blockIdx.y;
    int j0 = blockIdx.x * 128;

    if (t < CC) left_s[t] = g_left[(size_t)i * CC + t];

    /* copy precomputed B split (uint4) */
    {
        uint4* bh = (uint4*)Bthi;
        uint4* bl = (uint4*)Btlo;
        const uint4* gh = (const uint4*)g_bthi;
        const uint4* gl = (const uint4*)g_btlo;
        for (int idx = t; idx < 1600; idx += 512) { bh[idx] = gh[idx]; bl[idx] = gl[idx]; }
    }
    __syncthreads();

    /* H stage: 8 rounds x 16 warps -> 128 rows, 1-ahead prefetch */
    const float* pbase = pair + ((size_t)i * NN + j0) * PP;
    const float* rbase = g_right + (size_t)j0 * CC;
    float2 px = *(const float2*)(pbase + (size_t)wid * PP + 2 * lane);
    float4 rx = *(const float4*)(rbase + (size_t)wid * CC + 4 * lane);
    for (int r = 0; r < 8; ++r) {
        int e = r * 16 + wid;
        float2 cp = px; float4 cr = rx;
        if (r < 7) {
            px = *(const float2*)(pbase + (size_t)(e + 16) * PP + 2 * lane);
            rx = *(const float4*)(rbase + (size_t)(e + 16) * CC + 4 * lane);
        }
        /* LN(pair row) over 64 */
        float s = cp.x + cp.y, q = cp.x * cp.x + cp.y * cp.y;
#pragma unroll
        for (int off = 16; off; off >>= 1) {
            s += __shfl_xor_sync(0xffffffffu, s, off);
            q += __shfl_xor_sync(0xffffffffu, q, off);
        }
        float mu = s * (1.0f / PP);
        float rstd = rsqrtf(q * (1.0f / PP) - mu * mu + LNEPS);
        {
            uint32_t lo;
            uint32_t hi = pack_hi_split((cp.x - mu) * rstd, (cp.y - mu) * rstd, lo);
            Hhi[e * HSTRIDE + lane] = hi;
            Hlo[e * HSTRIDE + lane] = lo;
        }
        /* LN(left+right) over 128 */
        float y0 = left_s[4 * lane]     + cr.x;
        float y1 = left_s[4 * lane + 1] + cr.y;
        float y2 = left_s[4 * lane + 2] + cr.z;
        float y3 = left_s[4 * lane + 3] + cr.w;
        s = y0 + y1 + y2 + y3;
        q = y0 * y0 + y1 * y1 + y2 * y2 + y3 * y3;
#pragma unroll
        for (int off = 16; off; off >>= 1) {
            s += __shfl_xor_sync(0xffffffffu, s, off);
            q += __shfl_xor_sync(0xffffffffu, q, off);
        }
        mu = s * (1.0f / CC);
        rstd = rsqrtf(q * (1.0f / CC) - mu * mu + LNEPS);
        {
            uint32_t lo0, lo1;
            uint32_t hi0 = pack_hi_split((y0 - mu) * rstd, (y1 - mu) * rstd, lo0);
            uint32_t hi1 = pack_hi_split((y2 - mu) * rstd, (y3 - mu) * rstd, lo1);
            int wbase = e * HSTRIDE + 32 + 2 * lane;
            *(uint2*)(Hhi + wbase) = make_uint2(hi0, hi1);
            *(uint2*)(Hlo + wbase) = make_uint2(lo0, lo1);
        }
    }
    __syncthreads();

    /* MMA: warp -> m-tile (wid>>1), n-tiles (wid&1)*4..+3; 2 accum chains */
    int wr = (wid >> 1) * 16;
    int nb = (wid & 1) * 4;
    int grp = lane >> 2, qid = lane & 3;
    float acc1[4][4], acc2[4][4];
#pragma unroll
    for (int nt = 0; nt < 4; ++nt)
#pragma unroll
        for (int c = 0; c < 4; ++c) { acc1[nt][c] = 0.f; acc2[nt][c] = 0.f; }

#pragma unroll 2
    for (int ks = 0; ks < 12; ++ks) {
        int rb0 = (wr + grp) * HSTRIDE + ks * 8 + qid;
        int rb1 = rb0 + 8 * HSTRIDE;
        uint32_t ah0 = Hhi[rb0], ah1 = Hhi[rb1], ah2 = Hhi[rb0 + 4], ah3 = Hhi[rb1 + 4];
        uint32_t al0 = Hlo[rb0], al1 = Hlo[rb1], al2 = Hlo[rb0 + 4], al3 = Hlo[rb1 + 4];
#pragma unroll
        for (int nt = 0; nt < 4; ++nt) {
            int bo = ((nb + nt) * 8 + grp) * HSTRIDE + ks * 8 + qid;
            uint32_t bh0 = Bthi[bo], bh1 = Bthi[bo + 4];
            uint32_t bl0 = Btlo[bo], bl1 = Btlo[bo + 4];
            MMA_BF16(acc1[nt], ah0, ah1, ah2, ah3, bh0, bh1);
            MMA_BF16(acc2[nt], al0, al1, al2, al3, bh0, bh1);
            MMA_BF16(acc2[nt], ah0, ah1, ah2, ah3, bl0, bl1);
        }
    }

    /* store fragments */
    size_t orow0 = ((size_t)i * NN + j0 + wr + grp) * OO;
    size_t orow1 = orow0 + 8 * OO;
#pragma unroll
    for (int nt = 0; nt < 4; ++nt) {
        int col = (nb + nt) * 8 + qid * 2;
        *(float2*)(out + orow0 + col) =
            make_float2(acc1[nt][0] + acc2[nt][0], acc1[nt][1] + acc2[nt][1]);
        *(float2*)(out + orow1 + col) =
            make_float2(acc1[nt][2] + acc2[nt][2], acc1[nt][3] + acc2[nt][3]);
    }
}

/* ---------------- launch ---------------- */
extern "C" void kernel_launch(void* const* d_in, const int* in_sizes, int n_in,
                              void* d_out, int out_size)
{
    const float* local = (const float*)d_in[0];
    const float* pair  = (const float*)d_in[1];
    const int*   mask  = (const int*)d_in[2];
    const float* Wpg   = (const float*)d_in[3];
    const float* Wpv   = (const float*)d_in[4];
    const float* Wlg   = (const float*)d_in[5];
    const float* Wlv   = (const float*)d_in[6];
    const float* Wrg   = (const float*)d_in[7];
    const float* Wrv   = (const float*)d_in[8];
    const float* Wout  = (const float*)d_in[9];
    float* out = (float*)d_out;

    const int smem1 = (2 * PP * CC + 4 * TI * CC + 2 * 8 * PSTR + TI * CC) * 4;  /* 110848 */
    const int smem2 = SMEM2_FLOATS * 4;                                          /* 154112 */
    static bool attr_done = false;
    if (!attr_done) {
        cudaFuncSetAttribute(k_pass1, cudaFuncAttributeMaxDynamicSharedMemorySize, smem1);
        cudaFuncSetAttribute(k_pass2, cudaFuncAttributeMaxDynamicSharedMemorySize, smem2);
        attr_done = true;
    }

    k_zero<<<256, 256>>>();
    k_compact<<<1, NN>>>(mask);
    k_prepb<<<24, 256>>>(Wout);
    k_local<<<64, 128>>>(local, Wlg, Wlv, Wrg, Wrv);
    k_pass1<<<dim3(NN / TI, NN / TI), 256, smem1>>>(pair, Wpg, Wpv);
    k_pass2<<<dim3(NN / 128, NN), 512, smem2>>>(pair, out);
}

// round 6
// speedup vs baseline: 1.7611x; 1.2887x over previous
#include <cuda_runtime.h>
#include <cuda_bf16.h>
#include <math.h>
#include <stdint.h>

#define NN 512
#define LL 256
#define PP 64
#define CC 128   /* 2P */
#define HH 192   /* 3P */
#define OO 64
#define LNEPS 1e-5f

/* ---------------- scratch (no allocation allowed) ---------------- */
__device__ float g_lg[NN * CC];
__device__ float g_lv[NN * CC];
__device__ float g_rg[NN * CC];
__device__ float g_rv[NN * CC];
__device__ float g_left[NN * CC];
__device__ float g_right[NN * CC];
__device__ int   g_act[NN];
__device__ int   g_nact;

#define HSTRIDE 100
__device__ __align__(16) uint32_t g_bthi[OO * HSTRIDE];
__device__ __align__(16) uint32_t g_btlo[OO * HSTRIDE];

__device__ __forceinline__ float gelu_fast(float x) {
    /* jax.nn.gelu approximate=True, tanh via MUFU.TANH (abs err ~2^-11) */
    float u = 0.7978845608028654f * (x + 0.044715f * x * x * x);
    float th;
    asm("tanh.approx.f32 %0, %1;" : "=f"(th) : "f"(u));
    return 0.5f * x * (1.0f + th);
}

__device__ __forceinline__ uint32_t pack_hi_split(float x0, float x1, uint32_t& lo_out) {
    __nv_bfloat16 h0 = __float2bfloat16_rn(x0);
    __nv_bfloat16 h1 = __float2bfloat16_rn(x1);
    __nv_bfloat16 l0 = __float2bfloat16_rn(x0 - __bfloat162float(h0));
    __nv_bfloat16 l1 = __float2bfloat16_rn(x1 - __bfloat162float(h1));
    lo_out = ((uint32_t)__bfloat16_as_ushort(l1) << 16) | __bfloat16_as_ushort(l0);
    return ((uint32_t)__bfloat16_as_ushort(h1) << 16) | __bfloat16_as_ushort(h0);
}

#define MMA_BF16(acc, a0, a1, a2, a3, b0, b1) \
    asm volatile("mma.sync.aligned.m16n8k16.row.col.f32.bf16.bf16.f32 " \
        "{%0,%1,%2,%3}, {%4,%5,%6,%7}, {%8,%9}, {%0,%1,%2,%3};" \
        : "+f"((acc)[0]), "+f"((acc)[1]), "+f"((acc)[2]), "+f"((acc)[3]) \
        : "r"(a0), "r"(a1), "r"(a2), "r"(a3), "r"(b0), "r"(b1))

/* ---------------- kernel 0: zero accumulators ---------------- */
__global__ void k_zero() {
    int idx = blockIdx.x * blockDim.x + threadIdx.x;
    g_left[idx] = 0.0f;
    g_right[idx] = 0.0f;
}

/* ---------------- kernel 1: mask compaction ---------------- */
__global__ void k_compact(const int* __restrict__ mask) {
    __shared__ int s[NN];
    int t = threadIdx.x;
    int m = mask[t] ? 1 : 0;
    s[t] = m;
    __syncthreads();
#pragma unroll
    for (int off = 1; off < NN; off <<= 1) {
        int v = (t >= off) ? s[t - off] : 0;
        __syncthreads();
        s[t] += v;
        __syncthreads();
    }
    if (m) g_act[s[t] - 1] = t;
    if (t == NN - 1) g_nact = s[NN - 1];
}

/* ---------------- kernel 1b: Wout -> bf16 hi/lo split (once) ---------- */
__global__ void k_prepb(const float* __restrict__ Wout) {
    int idx = blockIdx.x * 256 + threadIdx.x;
    if (idx >= 96 * 64) return;
    int kp = idx >> 6, n = idx & 63;
    int k = kp * 2;
    uint32_t lo;
    uint32_t hi = pack_hi_split(Wout[k * OO + n], Wout[(k + 1) * OO + n], lo);
    g_bthi[n * HSTRIDE + kp] = hi;
    g_btlo[n * HSTRIDE + kp] = lo;
}

/* ---------------- kernel 2: LN(local) + 4 projections (parallelized) ----
   128 CTAs x 512 thr; 4 rows/CTA. Thread t: matrix m=t>>7, col c=t&127.
   LN rows transposed in smem so GEMV inner loop = LDS.128 + LDG + 4 FMA. */
__global__ void __launch_bounds__(512) k_local(
    const float* __restrict__ local,
    const float* __restrict__ Wlg, const float* __restrict__ Wlv,
    const float* __restrict__ Wrg, const float* __restrict__ Wrv)
{
    __shared__ float ln_s[LL * 4];      /* [k][r] transposed */
    __shared__ float rs[16], rq[16];
    int t = threadIdx.x;
    int row0 = blockIdx.x * 4;
    int rloc = t >> 7;                  /* 0..3: row handled by this 128-group */
    int c = t & 127;
    int lane = t & 31;

    /* LN: group rloc (4 warps) normalizes row row0+rloc */
    float x0 = local[(row0 + rloc) * LL + c];
    float x1 = local[(row0 + rloc) * LL + c + 128];
    float s = x0 + x1, q = x0 * x0 + x1 * x1;
#pragma unroll
    for (int off = 16; off; off >>= 1) {
        s += __shfl_xor_sync(0xffffffffu, s, off);
        q += __shfl_xor_sync(0xffffffffu, q, off);
    }
    if (lane == 0) { rs[t >> 5] = s; rq[t >> 5] = q; }
    __syncthreads();
    float st = rs[rloc * 4] + rs[rloc * 4 + 1] + rs[rloc * 4 + 2] + rs[rloc * 4 + 3];
    float qt = rq[rloc * 4] + rq[rloc * 4 + 1] + rq[rloc * 4 + 2] + rq[rloc * 4 + 3];
    float mu = st * (1.0f / LL);
    float rstd = rsqrtf(qt * (1.0f / LL) - mu * mu + LNEPS);
    ln_s[c * 4 + rloc]         = (x0 - mu) * rstd;
    ln_s[(c + 128) * 4 + rloc] = (x1 - mu) * rstd;
    __syncthreads();

    /* GEMV: matrix m = t>>7, col c; 4 row-accumulators; W stream from L2 */
    int m = t >> 7;
    const float* W = (m == 0) ? Wlg : (m == 1) ? Wlv : (m == 2) ? Wrg : Wrv;
    float* Op = (m == 0) ? g_lg : (m == 1) ? g_lv : (m == 2) ? g_rg : g_rv;
    float a0 = 0.f, a1 = 0.f, a2 = 0.f, a3 = 0.f;
#pragma unroll 8
    for (int k = 0; k < LL; ++k) {
        float w = W[k * CC + c];
        float4 l4 = *(const float4*)&ln_s[k * 4];
        a0 += l4.x * w; a1 += l4.y * w; a2 += l4.z * w; a3 += l4.w * w;
    }
    Op[(row0 + 0) * CC + c] = a0;
    Op[(row0 + 1) * CC + c] = a1;
    Op[(row0 + 2) * CC + c] = a2;
    Op[(row0 + 3) * CC + c] = a3;
}

/* ---------------- kernel 3: fused pass-1 ------------------------------
   thread map: cg = t>>3 (4 cols), el = t&7 (1 elem of 8-chunk)
   p_s double-buffered (stride 68), 1 sync per chunk.
   smem: 2*8192 + 4*2048 + 1088 + 2048 = 27712 floats = 110848 B -> 2 CTA/SM */
#define TI 16
#define PSTR 68
__global__ void __launch_bounds__(256, 2) k_pass1(
    const float* __restrict__ pair,
    const float* __restrict__ Wpg, const float* __restrict__ Wpv)
{
    extern __shared__ float sm[];
    float* Wg_s = sm;                       // 8192
    float* Wv_s = Wg_s + PP * CC;           // 8192
    float* lg_s = Wv_s + PP * CC;           // 2048
    float* lv_s = lg_s + TI * CC;
    float* rg_s = lv_s + TI * CC;
    float* rv_s = rg_s + TI * CC;
    float* p_s  = rv_s + TI * CC;           // 2*8*68 = 1088
    float* lacc = p_s + 2 * 8 * PSTR;       // 2048

    int nact = g_nact;
    int bi0 = blockIdx.x * TI, bj0 = blockIdx.y * TI;
    if (bi0 >= nact || bj0 >= nact) return;
    int ni = min(TI, nact - bi0), nj = min(TI, nact - bj0);
    int t = threadIdx.x;

    for (int idx = t; idx < PP * CC; idx += 256) { Wg_s[idx] = Wpg[idx]; Wv_s[idx] = Wpv[idx]; }
    for (int idx = t; idx < TI * CC; idx += 256) {
        int r = idx >> 7, cc = idx & 127;
        float a = 0.f, b = 0.f, cv = 0.f, d = 0.f;
        if (r < ni) { int gi = g_act[bi0 + r]; a = g_lg[gi * CC + cc]; b = g_rv[gi * CC + cc]; }
        if (r < nj) { int gj = g_act[bj0 + r]; cv = g_lv[gj * CC + cc]; d = g_rg[gj * CC + cc]; }
        lg_s[idx] = a; rv_s[idx] = b; lv_s[idx] = cv; rg_s[idx] = d;
    }
    for (int idx = t; idx < TI * CC; idx += 256) lacc[idx] = 0.f;
    __syncthreads();

    int cg = t >> 3;            // 0..31: cols cg*4..cg*4+3
    int el = t & 7;             // elem within 8-chunk
    int wid = t >> 5, lane = t & 31;
    const float4* wgq = (const float4*)Wg_s;
    const float4* wvq = (const float4*)Wv_s;
    float4 racc0 = make_float4(0, 0, 0, 0);
    float4 racc1 = make_float4(0, 0, 0, 0);

    for (int il = 0; il < ni; ++il) {
        int gi = g_act[bi0 + il];
        const float* prow = pair + (size_t)gi * NN * PP;
        float4 lg4 = *(const float4*)(lg_s + il * CC + cg * 4);
        float4 rv4 = *(const float4*)(rv_s + il * CC + cg * 4);
        float4 lsum = make_float4(0, 0, 0, 0);
#pragma unroll
        for (int jc = 0; jc < 2; ++jc) {
            int buf = (il * 2 + jc) & 1;
            /* LN: warp wid handles elem jl = jc*8+wid */
            int jl = jc * 8 + wid;
            float2 x = make_float2(0.f, 0.f);
            if (jl < nj) x = *(const float2*)(prow + (size_t)g_act[bj0 + jl] * PP + 2 * lane);
            float s = x.x + x.y, q = x.x * x.x + x.y * x.y;
#pragma unroll
            for (int off = 16; off; off >>= 1) {
                s += __shfl_xor_sync(0xffffffffu, s, off);
                q += __shfl_xor_sync(0xffffffffu, q, off);
            }
            float mu = s * (1.0f / PP);
            float rstd = rsqrtf(q * (1.0f / PP) - mu * mu + LNEPS);
            *(float2*)(p_s + buf * (8 * PSTR) + wid * PSTR + 2 * lane) =
                make_float2((x.x - mu) * rstd, (x.y - mu) * rstd);
            __syncthreads();

            /* GEMV: this thread -> elem el, cols cg*4..+3, both mats */
            const float* pp = p_s + buf * (8 * PSTR) + el * PSTR;
            float4 pg = make_float4(0, 0, 0, 0);
            float4 pv = make_float4(0, 0, 0, 0);
#pragma unroll 8
            for (int k = 0; k < PP; ++k) {
                float4 wg = wgq[k * 32 + cg];
                float4 wv = wvq[k * 32 + cg];
                float p = pp[k];
                pg.x += p * wg.x; pg.y += p * wg.y; pg.z += p * wg.z; pg.w += p * wg.w;
                pv.x += p * wv.x; pv.y += p * wv.y; pv.z += p * wv.z; pv.w += p * wv.w;
            }

            int jl2 = jc * 8 + el;
            if (jl2 < nj) {
                float4 lv4 = *(const float4*)(lv_s + jl2 * CC + cg * 4);
                float4 rg4 = *(const float4*)(rg_s + jl2 * CC + cg * 4);
                lsum.x += gelu_fast(lg4.x + pg.x) * (lv4.x + pv.x);
                lsum.y += gelu_fast(lg4.y + pg.y) * (lv4.y + pv.y);
                lsum.z += gelu_fast(lg4.z + pg.z) * (lv4.z + pv.z);
                lsum.w += gelu_fast(lg4.w + pg.w) * (lv4.w + pv.w);
                float4& ra = jc ? racc1 : racc0;
                ra.x += gelu_fast(rg4.x + pg.x) * (rv4.x + pv.x);
                ra.y += gelu_fast(rg4.y + pg.y) * (rv4.y + pv.y);
                ra.z += gelu_fast(rg4.z + pg.z) * (rv4.z + pv.z);
                ra.w += gelu_fast(rg4.w + pg.w) * (rv4.w + pv.w);
            }
        }
        /* reduce lsum over el (lane bits 0..2), single writer adds to lacc */
#pragma unroll
        for (int off = 1; off < 8; off <<= 1) {
            lsum.x += __shfl_xor_sync(0xffffffffu, lsum.x, off);
            lsum.y += __shfl_xor_sync(0xffffffffu, lsum.y, off);
            lsum.z += __shfl_xor_sync(0xffffffffu, lsum.z, off);
            lsum.w += __shfl_xor_sync(0xffffffffu, lsum.w, off);
        }
        if (el == 0) {
            float* lp = lacc + il * CC + cg * 4;
            lp[0] += lsum.x; lp[1] += lsum.y; lp[2] += lsum.z; lp[3] += lsum.w;
        }
    }

    /* flush right */
#pragma unroll
    for (int jc = 0; jc < 2; ++jc) {
        int jl = jc * 8 + el;
        if (jl < nj) {
            float* rp = &g_right[(size_t)g_act[bj0 + jl] * CC + cg * 4];
            float4 ra = jc ? racc1 : racc0;
            atomicAdd(rp + 0, ra.x);
            atomicAdd(rp + 1, ra.y);
            atomicAdd(rp + 2, ra.z);
            atomicAdd(rp + 3, ra.w);
        }
    }
    __syncthreads();
    /* flush left */
    for (int idx = t; idx < ni * CC; idx += 256) {
        int il = idx >> 7, cc = idx & 127;
        atomicAdd(&g_left[(size_t)g_act[bi0 + il] * CC + cc], lacc[idx]);
    }
}

/* ---------------- kernel 4: pass-2, 512 threads, split-chain HMMA ------ */
#define HHI_OFF  0
#define HLO_OFF  12800
#define BTHI_OFF 25600
#define BTLO_OFF 32000
#define LEFT_OFF 38400
#define SMEM2_FLOATS 38528

__global__ void __launch_bounds__(512) k_pass2(
    const float* __restrict__ pair,
    float* __restrict__ out)
{
    extern __shared__ float sm2[];
    uint32_t* Hhi  = (uint32_t*)(sm2 + HHI_OFF);
    uint32_t* Hlo  = (uint32_t*)(sm2 + HLO_OFF);
    uint32_t* Bthi = (uint32_t*)(sm2 + BTHI_OFF);
    uint32_t* Btlo = (uint32_t*)(sm2 + BTLO_OFF);
    float* left_s  = sm2 + LEFT_OFF;

    int t = threadIdx.x;
    int wid = t >> 5, lane = t & 31;
    int i = blockIdx.y;
    int j0 = blockIdx.x * 128;

    if (t < CC) left_s[t] = g_left[(size_t)i * CC + t];

    /* copy precomputed B split (uint4) */
    {
        uint4* bh = (uint4*)Bthi;
        uint4* bl = (uint4*)Btlo;
        const uint4* gh = (const uint4*)g_bthi;
        const uint4* gl = (const uint4*)g_btlo;
        for (int idx = t; idx < 1600; idx += 512) { bh[idx] = gh[idx]; bl[idx] = gl[idx]; }
    }
    __syncthreads();

    /* H stage: 8 rounds x 16 warps -> 128 rows, 1-ahead prefetch */
    const float* pbase = pair + ((size_t)i * NN + j0) * PP;
    const float* rbase = g_right + (size_t)j0 * CC;
    float2 px = *(const float2*)(pbase + (size_t)wid * PP + 2 * lane);
    float4 rx = *(const float4*)(rbase + (size_t)wid * CC + 4 * lane);
    for (int r = 0; r < 8; ++r) {
        int e = r * 16 + wid;
        float2 cp = px; float4 cr = rx;
        if (r < 7) {
            px = *(const float2*)(pbase + (size_t)(e + 16) * PP + 2 * lane);
            rx = *(const float4*)(rbase + (size_t)(e + 16) * CC + 4 * lane);
        }
        /* LN(pair row) over 64 */
        float s = cp.x + cp.y, q = cp.x * cp.x + cp.y * cp.y;
#pragma unroll
        for (int off = 16; off; off >>= 1) {
            s += __shfl_xor_sync(0xffffffffu, s, off);
            q += __shfl_xor_sync(0xffffffffu, q, off);
        }
        float mu = s * (1.0f / PP);
        float rstd = rsqrtf(q * (1.0f / PP) - mu * mu + LNEPS);
        {
            uint32_t lo;
            uint32_t hi = pack_hi_split((cp.x - mu) * rstd, (cp.y - mu) * rstd, lo);
            Hhi[e * HSTRIDE + lane] = hi;
            Hlo[e * HSTRIDE + lane] = lo;
        }
        /* LN(left+right) over 128 */
        float y0 = left_s[4 * lane]     + cr.x;
        float y1 = left_s[4 * lane + 1] + cr.y;
        float y2 = left_s[4 * lane + 2] + cr.z;
        float y3 = left_s[4 * lane + 3] + cr.w;
        s = y0 + y1 + y2 + y3;
        q = y0 * y0 + y1 * y1 + y2 * y2 + y3 * y3;
#pragma unroll
        for (int off = 16; off; off >>= 1) {
            s += __shfl_xor_sync(0xffffffffu, s, off);
            q += __shfl_xor_sync(0xffffffffu, q, off);
        }
        mu = s * (1.0f / CC);
        rstd = rsqrtf(q * (1.0f / CC) - mu * mu + LNEPS);
        {
            uint32_t lo0, lo1;
            uint32_t hi0 = pack_hi_split((y0 - mu) * rstd, (y1 - mu) * rstd, lo0);
            uint32_t hi1 = pack_hi_split((y2 - mu) * rstd, (y3 - mu) * rstd, lo1);
            int wbase = e * HSTRIDE + 32 + 2 * lane;
            *(uint2*)(Hhi + wbase) = make_uint2(hi0, hi1);
            *(uint2*)(Hlo + wbase) = make_uint2(lo0, lo1);
        }
    }
    __syncthreads();

    /* MMA: warp -> m-tile (wid>>1), n-tiles (wid&1)*4..+3; 2 accum chains */
    int wr = (wid >> 1) * 16;
    int nb = (wid & 1) * 4;
    int grp = lane >> 2, qid = lane & 3;
    float acc1[4][4], acc2[4][4];
#pragma unroll
    for (int nt = 0; nt < 4; ++nt)
#pragma unroll
        for (int c = 0; c < 4; ++c) { acc1[nt][c] = 0.f; acc2[nt][c] = 0.f; }

#pragma unroll 2
    for (int ks = 0; ks < 12; ++ks) {
        int rb0 = (wr + grp) * HSTRIDE + ks * 8 + qid;
        int rb1 = rb0 + 8 * HSTRIDE;
        uint32_t ah0 = Hhi[rb0], ah1 = Hhi[rb1], ah2 = Hhi[rb0 + 4], ah3 = Hhi[rb1 + 4];
        uint32_t al0 = Hlo[rb0], al1 = Hlo[rb1], al2 = Hlo[rb0 + 4], al3 = Hlo[rb1 + 4];
#pragma unroll
        for (int nt = 0; nt < 4; ++nt) {
            int bo = ((nb + nt) * 8 + grp) * HSTRIDE + ks * 8 + qid;
            uint32_t bh0 = Bthi[bo], bh1 = Bthi[bo + 4];
            uint32_t bl0 = Btlo[bo], bl1 = Btlo[bo + 4];
            MMA_BF16(acc1[nt], ah0, ah1, ah2, ah3, bh0, bh1);
            MMA_BF16(acc2[nt], al0, al1, al2, al3, bh0, bh1);
            MMA_BF16(acc2[nt], ah0, ah1, ah2, ah3, bl0, bl1);
        }
    }

    /* store fragments */
    size_t orow0 = ((size_t)i * NN + j0 + wr + grp) * OO;
    size_t orow1 = orow0 + 8 * OO;
#pragma unroll
    for (int nt = 0; nt < 4; ++nt) {
        int col = (nb + nt) * 8 + qid * 2;
        *(float2*)(out + orow0 + col) =
            make_float2(acc1[nt][0] + acc2[nt][0], acc1[nt][1] + acc2[nt][1]);
        *(float2*)(out + orow1 + col) =
            make_float2(acc1[nt][2] + acc2[nt][2], acc1[nt][3] + acc2[nt][3]);
    }
}

/* ---------------- launch ---------------- */
extern "C" void kernel_launch(void* const* d_in, const int* in_sizes, int n_in,
                              void* d_out, int out_size)
{
    const float* local = (const float*)d_in[0];
    const float* pair  = (const float*)d_in[1];
    const int*   mask  = (const int*)d_in[2];
    const float* Wpg   = (const float*)d_in[3];
    const float* Wpv   = (const float*)d_in[4];
    const float* Wlg   = (const float*)d_in[5];
    const float* Wlv   = (const float*)d_in[6];
    const float* Wrg   = (const float*)d_in[7];
    const float* Wrv   = (const float*)d_in[8];
    const float* Wout  = (const float*)d_in[9];
    float* out = (float*)d_out;

    const int smem1 = (2 * PP * CC + 4 * TI * CC + 2 * 8 * PSTR + TI * CC) * 4;  /* 110848 */
    const int smem2 = SMEM2_FLOATS * 4;                                          /* 154112 */
    static bool attr_done = false;
    if (!attr_done) {
        cudaFuncSetAttribute(k_pass1, cudaFuncAttributeMaxDynamicSharedMemorySize, smem1);
        cudaFuncSetAttribute(k_pass2, cudaFuncAttributeMaxDynamicSharedMemorySize, smem2);
        attr_done = true;
    }

    k_zero<<<256, 256>>>();
    k_compact<<<1, NN>>>(mask);
    k_prepb<<<24, 256>>>(Wout);
    k_local<<<128, 512>>>(local, Wlg, Wlv, Wrg, Wrv);
    k_pass1<<<dim3(NN / TI, NN / TI), 256, smem1>>>(pair, Wpg, Wpv);
    k_pass2<<<dim3(NN / 128, NN), 512, smem2>>>(pair, out);
}

// round 7
// speedup vs baseline: 1.7694x; 1.0047x over previous
#include <cuda_runtime.h>
#include <cuda_bf16.h>
#include <math.h>
#include <stdint.h>

#define NN 512
#define LL 256
#define PP 64
#define CC 128   /* 2P */
#define HH 192   /* 3P */
#define OO 64
#define LNEPS 1e-5f

/* ---------------- scratch (no allocation allowed) ---------------- */
__device__ float g_lg[NN * CC];
__device__ float g_lv[NN * CC];
__device__ float g_rg[NN * CC];
__device__ float g_rv[NN * CC];
__device__ float g_left[NN * CC];
__device__ float g_right[NN * CC];
__device__ int   g_act[NN];
__device__ int   g_nact;

#define BST 196   /* padded k-stride for tf32 B/H (192 + 4) */
__device__ __align__(16) uint32_t g_bt[OO * BST];

__device__ __forceinline__ float gelu_fast(float x) {
    /* jax.nn.gelu approximate=True, tanh via MUFU.TANH (abs err ~2^-11) */
    float u = 0.7978845608028654f * (x + 0.044715f * x * x * x);
    float th;
    asm("tanh.approx.f32 %0, %1;" : "=f"(th) : "f"(u));
    return 0.5f * x * (1.0f + th);
}

__device__ __forceinline__ uint32_t f2tf32(float x) {
    uint32_t r;
    asm("cvt.rna.tf32.f32 %0, %1;" : "=r"(r) : "f"(x));
    return r;
}

#define MMA_TF32(acc, a0, a1, a2, a3, b0, b1) \
    asm volatile("mma.sync.aligned.m16n8k8.row.col.f32.tf32.tf32.f32 " \
        "{%0,%1,%2,%3}, {%4,%5,%6,%7}, {%8,%9}, {%0,%1,%2,%3};" \
        : "+f"((acc)[0]), "+f"((acc)[1]), "+f"((acc)[2]), "+f"((acc)[3]) \
        : "r"(a0), "r"(a1), "r"(a2), "r"(a3), "r"(b0), "r"(b1))

/* ---------------- kernel 0: zero accumulators ---------------- */
__global__ void k_zero() {
    int idx = blockIdx.x * blockDim.x + threadIdx.x;
    g_left[idx] = 0.0f;
    g_right[idx] = 0.0f;
}

/* ---------------- kernel 1: mask compaction ---------------- */
__global__ void k_compact(const int* __restrict__ mask) {
    __shared__ int s[NN];
    int t = threadIdx.x;
    int m = mask[t] ? 1 : 0;
    s[t] = m;
    __syncthreads();
#pragma unroll
    for (int off = 1; off < NN; off <<= 1) {
        int v = (t >= off) ? s[t - off] : 0;
        __syncthreads();
        s[t] += v;
        __syncthreads();
    }
    if (m) g_act[s[t] - 1] = t;
    if (t == NN - 1) g_nact = s[NN - 1];
}

/* ---------------- kernel 1b: Wout^T -> tf32 (once) ---------- */
__global__ void k_prepb(const float* __restrict__ Wout) {
    int idx = blockIdx.x * 256 + threadIdx.x;
    if (idx >= HH * OO) return;
    int k = idx >> 6, n = idx & 63;
    g_bt[n * BST + k] = f2tf32(Wout[k * OO + n]);
}

/* ---------------- kernel 2: LN(local) + 4 projections (parallelized) ----
   128 CTAs x 512 thr; 4 rows/CTA. Thread t: matrix m=t>>7, col c=t&127. */
__global__ void __launch_bounds__(512) k_local(
    const float* __restrict__ local,
    const float* __restrict__ Wlg, const float* __restrict__ Wlv,
    const float* __restrict__ Wrg, const float* __restrict__ Wrv)
{
    __shared__ float ln_s[LL * 4];      /* [k][r] transposed */
    __shared__ float rs[16], rq[16];
    int t = threadIdx.x;
    int row0 = blockIdx.x * 4;
    int rloc = t >> 7;
    int c = t & 127;
    int lane = t & 31;

    float x0 = local[(row0 + rloc) * LL + c];
    float x1 = local[(row0 + rloc) * LL + c + 128];
    float s = x0 + x1, q = x0 * x0 + x1 * x1;
#pragma unroll
    for (int off = 16; off; off >>= 1) {
        s += __shfl_xor_sync(0xffffffffu, s, off);
        q += __shfl_xor_sync(0xffffffffu, q, off);
    }
    if (lane == 0) { rs[t >> 5] = s; rq[t >> 5] = q; }
    __syncthreads();
    float st = rs[rloc * 4] + rs[rloc * 4 + 1] + rs[rloc * 4 + 2] + rs[rloc * 4 + 3];
    float qt = rq[rloc * 4] + rq[rloc * 4 + 1] + rq[rloc * 4 + 2] + rq[rloc * 4 + 3];
    float mu = st * (1.0f / LL);
    float rstd = rsqrtf(qt * (1.0f / LL) - mu * mu + LNEPS);
    ln_s[c * 4 + rloc]         = (x0 - mu) * rstd;
    ln_s[(c + 128) * 4 + rloc] = (x1 - mu) * rstd;
    __syncthreads();

    int m = t >> 7;
    const float* W = (m == 0) ? Wlg : (m == 1) ? Wlv : (m == 2) ? Wrg : Wrv;
    float* Op = (m == 0) ? g_lg : (m == 1) ? g_lv : (m == 2) ? g_rg : g_rv;
    float a0 = 0.f, a1 = 0.f, a2 = 0.f, a3 = 0.f;
#pragma unroll 8
    for (int k = 0; k < LL; ++k) {
        float w = W[k * CC + c];
        float4 l4 = *(const float4*)&ln_s[k * 4];
        a0 += l4.x * w; a1 += l4.y * w; a2 += l4.z * w; a3 += l4.w * w;
    }
    Op[(row0 + 0) * CC + c] = a0;
    Op[(row0 + 1) * CC + c] = a1;
    Op[(row0 + 2) * CC + c] = a2;
    Op[(row0 + 3) * CC + c] = a3;
}

/* ---------------- kernel 3: fused pass-1 (unchanged this round) -------- */
#define TI 16
#define PSTR 68
__global__ void __launch_bounds__(256, 2) k_pass1(
    const float* __restrict__ pair,
    const float* __restrict__ Wpg, const float* __restrict__ Wpv)
{
    extern __shared__ float sm[];
    float* Wg_s = sm;                       // 8192
    float* Wv_s = Wg_s + PP * CC;           // 8192
    float* lg_s = Wv_s + PP * CC;           // 2048
    float* lv_s = lg_s + TI * CC;
    float* rg_s = lv_s + TI * CC;
    float* rv_s = rg_s + TI * CC;
    float* p_s  = rv_s + TI * CC;           // 2*8*68 = 1088
    float* lacc = p_s + 2 * 8 * PSTR;       // 2048

    int nact = g_nact;
    int bi0 = blockIdx.x * TI, bj0 = blockIdx.y * TI;
    if (bi0 >= nact || bj0 >= nact) return;
    int ni = min(TI, nact - bi0), nj = min(TI, nact - bj0);
    int t = threadIdx.x;

    for (int idx = t; idx < PP * CC; idx += 256) { Wg_s[idx] = Wpg[idx]; Wv_s[idx] = Wpv[idx]; }
    for (int idx = t; idx < TI * CC; idx += 256) {
        int r = idx >> 7, cc = idx & 127;
        float a = 0.f, b = 0.f, cv = 0.f, d = 0.f;
        if (r < ni) { int gi = g_act[bi0 + r]; a = g_lg[gi * CC + cc]; b = g_rv[gi * CC + cc]; }
        if (r < nj) { int gj = g_act[bj0 + r]; cv = g_lv[gj * CC + cc]; d = g_rg[gj * CC + cc]; }
        lg_s[idx] = a; rv_s[idx] = b; lv_s[idx] = cv; rg_s[idx] = d;
    }
    for (int idx = t; idx < TI * CC; idx += 256) lacc[idx] = 0.f;
    __syncthreads();

    int cg = t >> 3;
    int el = t & 7;
    int wid = t >> 5, lane = t & 31;
    const float4* wgq = (const float4*)Wg_s;
    const float4* wvq = (const float4*)Wv_s;
    float4 racc0 = make_float4(0, 0, 0, 0);
    float4 racc1 = make_float4(0, 0, 0, 0);

    for (int il = 0; il < ni; ++il) {
        int gi = g_act[bi0 + il];
        const float* prow = pair + (size_t)gi * NN * PP;
        float4 lg4 = *(const float4*)(lg_s + il * CC + cg * 4);
        float4 rv4 = *(const float4*)(rv_s + il * CC + cg * 4);
        float4 lsum = make_float4(0, 0, 0, 0);
#pragma unroll
        for (int jc = 0; jc < 2; ++jc) {
            int buf = (il * 2 + jc) & 1;
            int jl = jc * 8 + wid;
            float2 x = make_float2(0.f, 0.f);
            if (jl < nj) x = *(const float2*)(prow + (size_t)g_act[bj0 + jl] * PP + 2 * lane);
            float s = x.x + x.y, q = x.x * x.x + x.y * x.y;
#pragma unroll
            for (int off = 16; off; off >>= 1) {
                s += __shfl_xor_sync(0xffffffffu, s, off);
                q += __shfl_xor_sync(0xffffffffu, q, off);
            }
            float mu = s * (1.0f / PP);
            float rstd = rsqrtf(q * (1.0f / PP) - mu * mu + LNEPS);
            *(float2*)(p_s + buf * (8 * PSTR) + wid * PSTR + 2 * lane) =
                make_float2((x.x - mu) * rstd, (x.y - mu) * rstd);
            __syncthreads();

            const float* pp = p_s + buf * (8 * PSTR) + el * PSTR;
            float4 pg = make_float4(0, 0, 0, 0);
            float4 pv = make_float4(0, 0, 0, 0);
#pragma unroll 8
            for (int k = 0; k < PP; ++k) {
                float4 wg = wgq[k * 32 + cg];
                float4 wv = wvq[k * 32 + cg];
                float p = pp[k];
                pg.x += p * wg.x; pg.y += p * wg.y; pg.z += p * wg.z; pg.w += p * wg.w;
                pv.x += p * wv.x; pv.y += p * wv.y; pv.z += p * wv.z; pv.w += p * wv.w;
            }

            int jl2 = jc * 8 + el;
            if (jl2 < nj) {
                float4 lv4 = *(const float4*)(lv_s + jl2 * CC + cg * 4);
                float4 rg4 = *(const float4*)(rg_s + jl2 * CC + cg * 4);
                lsum.x += gelu_fast(lg4.x + pg.x) * (lv4.x + pv.x);
                lsum.y += gelu_fast(lg4.y + pg.y) * (lv4.y + pv.y);
                lsum.z += gelu_fast(lg4.z + pg.z) * (lv4.z + pv.z);
                lsum.w += gelu_fast(lg4.w + pg.w) * (lv4.w + pv.w);
                float4& ra = jc ? racc1 : racc0;
                ra.x += gelu_fast(rg4.x + pg.x) * (rv4.x + pv.x);
                ra.y += gelu_fast(rg4.y + pg.y) * (rv4.y + pv.y);
                ra.z += gelu_fast(rg4.z + pg.z) * (rv4.z + pv.z);
                ra.w += gelu_fast(rg4.w + pg.w) * (rv4.w + pv.w);
            }
        }
#pragma unroll
        for (int off = 1; off < 8; off <<= 1) {
            lsum.x += __shfl_xor_sync(0xffffffffu, lsum.x, off);
            lsum.y += __shfl_xor_sync(0xffffffffu, lsum.y, off);
            lsum.z += __shfl_xor_sync(0xffffffffu, lsum.z, off);
            lsum.w += __shfl_xor_sync(0xffffffffu, lsum.w, off);
        }
        if (el == 0) {
            float* lp = lacc + il * CC + cg * 4;
            lp[0] += lsum.x; lp[1] += lsum.y; lp[2] += lsum.z; lp[3] += lsum.w;
        }
    }

#pragma unroll
    for (int jc = 0; jc < 2; ++jc) {
        int jl = jc * 8 + el;
        if (jl < nj) {
            float* rp = &g_right[(size_t)g_act[bj0 + jl] * CC + cg * 4];
            float4 ra = jc ? racc1 : racc0;
            atomicAdd(rp + 0, ra.x);
            atomicAdd(rp + 1, ra.y);
            atomicAdd(rp + 2, ra.z);
            atomicAdd(rp + 3, ra.w);
        }
    }
    __syncthreads();
    for (int idx = t; idx < ni * CC; idx += 256) {
        int il = idx >> 7, cc = idx & 127;
        atomicAdd(&g_left[(size_t)g_act[bi0 + il] * CC + cc], lacc[idx]);
    }
}

/* ---------------- kernel 4: pass-2, single-pass tf32 HMMA -------------
   H [128 x 192] tf32 in smem (stride 196), B = Wout^T [64 x 192] tf32.
   16 warps: m-tile = wid>>1 (16 rows), n-half = (wid&1)*4 n-tiles.       */
#define HS_OFF   0
#define BS_OFF   25088            /* 128*196 */
#define LEFT_OFF 37632            /* + 64*196 */
#define SMEM2_FLOATS 37760

__global__ void __launch_bounds__(512) k_pass2(
    const float* __restrict__ pair,
    float* __restrict__ out)
{
    extern __shared__ float sm2[];
    uint32_t* Hs = (uint32_t*)(sm2 + HS_OFF);
    uint32_t* Bs = (uint32_t*)(sm2 + BS_OFF);
    float* left_s = sm2 + LEFT_OFF;

    int t = threadIdx.x;
    int wid = t >> 5, lane = t & 31;
    int i = blockIdx.y;
    int j0 = blockIdx.x * 128;

    if (t < CC) left_s[t] = g_left[(size_t)i * CC + t];

    /* copy precomputed tf32 B (64*196 = 12544 words, uint4) */
    {
        uint4* bs4 = (uint4*)Bs;
        const uint4* gb4 = (const uint4*)g_bt;
        for (int idx = t; idx < 3136; idx += 512) bs4[idx] = gb4[idx];
    }
    __syncthreads();

    /* H stage: 8 rounds x 16 warps -> 128 rows, 1-ahead prefetch */
    const float* pbase = pair + ((size_t)i * NN + j0) * PP;
    const float* rbase = g_right + (size_t)j0 * CC;
    float2 px = *(const float2*)(pbase + (size_t)wid * PP + 2 * lane);
    float4 rx = *(const float4*)(rbase + (size_t)wid * CC + 4 * lane);
    for (int r = 0; r < 8; ++r) {
        int e = r * 16 + wid;
        float2 cp = px; float4 cr = rx;
        if (r < 7) {
            px = *(const float2*)(pbase + (size_t)(e + 16) * PP + 2 * lane);
            rx = *(const float4*)(rbase + (size_t)(e + 16) * CC + 4 * lane);
        }
        /* LN(pair row) over 64 */
        float s = cp.x + cp.y, q = cp.x * cp.x + cp.y * cp.y;
#pragma unroll
        for (int off = 16; off; off >>= 1) {
            s += __shfl_xor_sync(0xffffffffu, s, off);
            q += __shfl_xor_sync(0xffffffffu, q, off);
        }
        float mu = s * (1.0f / PP);
        float rstd = rsqrtf(q * (1.0f / PP) - mu * mu + LNEPS);
        {
            uint2 w = make_uint2(f2tf32((cp.x - mu) * rstd), f2tf32((cp.y - mu) * rstd));
            *(uint2*)(Hs + e * BST + 2 * lane) = w;
        }
        /* LN(left+right) over 128 */
        float y0 = left_s[4 * lane]     + cr.x;
        float y1 = left_s[4 * lane + 1] + cr.y;
        float y2 = left_s[4 * lane + 2] + cr.z;
        float y3 = left_s[4 * lane + 3] + cr.w;
        s = y0 + y1 + y2 + y3;
        q = y0 * y0 + y1 * y1 + y2 * y2 + y3 * y3;
#pragma unroll
        for (int off = 16; off; off >>= 1) {
            s += __shfl_xor_sync(0xffffffffu, s, off);
            q += __shfl_xor_sync(0xffffffffu, q, off);
        }
        mu = s * (1.0f / CC);
        rstd = rsqrtf(q * (1.0f / CC) - mu * mu + LNEPS);
        {
            uint4 w = make_uint4(f2tf32((y0 - mu) * rstd), f2tf32((y1 - mu) * rstd),
                                 f2tf32((y2 - mu) * rstd), f2tf32((y3 - mu) * rstd));
            *(uint4*)(Hs + e * BST + 64 + 4 * lane) = w;
        }
    }
    __syncthreads();

    /* MMA: 24 k8-steps x 4 n-tiles per warp */
    int wr = (wid >> 1) * 16;
    int nb = (wid & 1) * 4;
    int grp = lane >> 2, qid = lane & 3;
    float acc[4][4];
#pragma unroll
    for (int nt = 0; nt < 4; ++nt)
#pragma unroll
        for (int c = 0; c < 4; ++c) acc[nt][c] = 0.f;

    int ar0 = (wr + grp) * BST + qid;
    int ar1 = ar0 + 8 * BST;
#pragma unroll 4
    for (int ks = 0; ks < 24; ++ks) {
        int ko = ks * 8;
        uint32_t a0 = Hs[ar0 + ko], a1 = Hs[ar1 + ko];
        uint32_t a2 = Hs[ar0 + ko + 4], a3 = Hs[ar1 + ko + 4];
#pragma unroll
        for (int nt = 0; nt < 4; ++nt) {
            int bo = ((nb + nt) * 8 + grp) * BST + ko + qid;
            uint32_t b0 = Bs[bo], b1 = Bs[bo + 4];
            MMA_TF32(acc[nt], a0, a1, a2, a3, b0, b1);
        }
    }

    /* store fragments */
    size_t orow0 = ((size_t)i * NN + j0 + wr + grp) * OO;
    size_t orow1 = orow0 + 8 * OO;
#pragma unroll
    for (int nt = 0; nt < 4; ++nt) {
        int col = (nb + nt) * 8 + qid * 2;
        *(float2*)(out + orow0 + col) = make_float2(acc[nt][0], acc[nt][1]);
        *(float2*)(out + orow1 + col) = make_float2(acc[nt][2], acc[nt][3]);
    }
}

/* ---------------- launch ---------------- */
extern "C" void kernel_launch(void* const* d_in, const int* in_sizes, int n_in,
                              void* d_out, int out_size)
{
    const float* local = (const float*)d_in[0];
    const float* pair  = (const float*)d_in[1];
    const int*   mask  = (const int*)d_in[2];
    const float* Wpg   = (const float*)d_in[3];
    const float* Wpv   = (const float*)d_in[4];
    const float* Wlg   = (const float*)d_in[5];
    const float* Wlv   = (const float*)d_in[6];
    const float* Wrg   = (const float*)d_in[7];
    const float* Wrv   = (const float*)d_in[8];
    const float* Wout  = (const float*)d_in[9];
    float* out = (float*)d_out;

    const int smem1 = (2 * PP * CC + 4 * TI * CC + 2 * 8 * PSTR + TI * CC) * 4;  /* 110848 */
    const int smem2 = SMEM2_FLOATS * 4;                                          /* 151040 */
    static bool attr_done = false;
    if (!attr_done) {
        cudaFuncSetAttribute(k_pass1, cudaFuncAttributeMaxDynamicSharedMemorySize, smem1);
        cudaFuncSetAttribute(k_pass2, cudaFuncAttributeMaxDynamicSharedMemorySize, smem2);
        attr_done = true;
    }

    k_zero<<<256, 256>>>();
    k_compact<<<1, NN>>>(mask);
    k_prepb<<<48, 256>>>(Wout);
    k_local<<<128, 512>>>(local, Wlg, Wlv, Wrg, Wrv);
    k_pass1<<<dim3(NN / TI, NN / TI), 256, smem1>>>(pair, Wpg, Wpv);
    k_pass2<<<dim3(NN / 128, NN), 512, smem2>>>(pair, out);
}